// round 7
// baseline (speedup 1.0000x reference)
#include <cuda_runtime.h>
#include <math.h>

#define PI_D 3.14159265358979323846264338327950288

typedef unsigned long long u64;

// packed fp32x2 FMA: acc = a*b + acc (elementwise on both 32-bit halves)
#define FMA2(acc, a, b) asm("fma.rn.f32x2 %0, %1, %2, %0;" : "+l"(acc) : "l"(a), "l"(b))

__device__ __forceinline__ u64 pk2(float x, float y) {
    u64 r; asm("mov.b64 %0, {%1, %2};" : "=l"(r) : "f"(x), "f"(y)); return r;
}
__device__ __forceinline__ void upk2(u64 v, float& x, float& y) {
    asm("mov.b64 {%0, %1}, %2;" : "=f"(x), "=f"(y) : "l"(v));
}

// Problem sizes: L=256, 2L-1=511, C=32, L_FREQ=128, MF=255, T_DIM=256

// ---------------- scratch (device globals; allocation-free) ----------------
__device__ float  g_P [16777216];              // [m][l][t]  256*256*256, zero for l<m
__device__ float  g_w [256];                   // quadrature weights sin(th)*dang^2
__device__ float  g_cs[256];                   // sqrt((2k+1)/(2k))
__device__ float2 g_ab[65536];                 // [m][l] recurrence coeffs (a,b)
__device__ __align__(16) float2 g_T[65536];    // [k][j] (cos,sin)(2*pi*k*j/511), k,j<256
__device__ __align__(16) float  g_xs[2097152]; // [p][t][c] folded+weighted x (sum)
__device__ __align__(16) float  g_xd[2097152]; // [p][t][c] folded+weighted x (diff)
__device__ __align__(16) float  g_Fr[2097152]; // [m][t][c]
__device__ __align__(16) float  g_Fi[2097152];
__device__ float  g_fr[2097152];               // [m][l][c] flm for m>=0
__device__ float  g_fi[2097152];
__device__ float  g_Ar[1044480];               // [lo][mo][c] resized flm
__device__ float  g_Ai[1044480];
__device__ float  g_Wr[131072];                // [l][i][o] modulated weight
__device__ float  g_Wi[131072];
__device__ float  g_Br[1044480];               // [mi][l][c] after channel mix
__device__ float  g_Bi[1044480];
__device__ float  g_Gr[2088960];               // [mi][t][c]
__device__ float  g_Gi[2088960];
__device__ __align__(16) float  g_Hc[1048576]; // [mu][t][c] m-folded cos coeff
__device__ __align__(16) float  g_Hs[1048576]; // [mu][t][c] m-folded sin coeff

// ---------------- recurrence coefficients (MUFU-heavy, tiny) ----------------
__global__ void k_coef() {
    int m = blockIdx.x, l = threadIdx.x;
    if (m == 0) {
        g_cs[l] = (l >= 1) ? sqrtf((2.f * l + 1.f) / (2.f * l)) : 0.f;
    }
    float2 ab = make_float2(0.f, 0.f);
    if (l >= m + 2) {
        float fl = (float)l, fm = (float)m;
        float denom = fl * fl - fm * fm;
        ab.x = sqrtf((4.f * fl * fl - 1.f) / denom);
        ab.y = sqrtf((2.f * fl + 1.f) * (fl - 1.f - fm) * (fl - 1.f + fm) /
                     ((2.f * fl - 3.f) * denom));
    }
    g_ab[m * 256 + l] = ab;
}

// ---------------- basis: pure-FMA recurrence using precomputed coeffs ----------------
__global__ void k_basis() {
    int m = blockIdx.x;
    int t = threadIdx.x;
    __shared__ float  cs[256];
    __shared__ float2 ab[256];
    cs[t] = g_cs[t];
    ab[t] = g_ab[m * 256 + t];
    double th = PI_D * (2.0 * t + 1.0) / 511.0;
    float ct = (float)cos(th), st = (float)sin(th);
    if (m == 0) {
        double dang = 2.0 * PI_D / 511.0;
        g_w[t] = (float)(sin(th) * dang * dang);
    }
    __syncthreads();
    float* Pm = g_P + m * 65536;
    for (int l = 0; l < m; l++) Pm[l * 256 + t] = 0.f;
    float pmm = 0.28209479177387814f;  // sqrt(1/(4*pi))
    for (int k = 1; k <= m; k++) pmm *= -cs[k] * st;
    Pm[m * 256 + t] = pmm;
    if (m + 1 < 256) {
        float pl1 = sqrtf(2.f * m + 3.f) * ct * pmm;
        Pm[(m + 1) * 256 + t] = pl1;
        float pl2 = pmm;
        for (int l = m + 2; l < 256; l++) {
            float2 c2 = ab[l];
            float p = c2.x * ct * pl1 - c2.y * pl2;
            Pm[l * 256 + t] = p;
            pl2 = pl1; pl1 = p;
        }
    }
}

// ---------------- twiddle table: (cos,sin)(2*pi*k*j/511), k,j in 0..255 ----------------
__global__ void k_ttab() {
    int k = blockIdx.x, j = threadIdx.x;
    int kj = (k * j) % 511;
    double s, c;
    sincos(2.0 * PI_D * (double)kj / 511.0, &s, &c);
    g_T[k * 256 + j] = make_float2((float)c, (float)s);
}

// ---------------- fold x over p-pairs, apply quadrature weight ----------------
__global__ void k_fold1(const float* __restrict__ x) {
    int p = blockIdx.y;
    int tid = threadIdx.x;
    int t = blockIdx.x * 8 + (tid >> 5);
    int c = tid & 31;
    float w = g_w[t];
    float a = x[((size_t)t * 511 + p) * 32 + c];
    float xs, xd;
    if (p == 0) { xs = w * a; xd = 0.f; }
    else {
        float b = x[((size_t)t * 511 + (511 - p)) * 32 + c];
        xs = w * (a + b);
        xd = w * (b - a);
    }
    size_t o = ((size_t)p * 256 + t) * 32 + c;
    g_xs[o] = xs;
    g_xd[o] = xd;
}

// ---------------- tiled dual-GEMM with packed f32x2 FMA ----------------
// A = g_T (cos,sin) pairs; B interleaved (b1,b2) pairs in smem.
// acc pair = (Cr, Ci): acc += (co,si) ⊙ (b1,b2).
// MODE 0: B1=g_xs, B2=g_xd -> g_Fr, g_Fi (forward DFT)
// MODE 1: B1=g_Hc, B2=g_Hs -> out with p-fold epilogue
template<int KTOT, int MODE>
__global__ void __launch_bounds__(256)
k_gemm(float* __restrict__ outp) {
    const float* __restrict__ B1 = (MODE == 0) ? g_xs : g_Hc;
    const float* __restrict__ B2 = (MODE == 0) ? g_xd : g_Hs;
    __shared__ __align__(16) float2 As[16][64];
    __shared__ __align__(16) float2 Bs[16][64];
    const int tid = threadIdx.x;
    const int m0 = blockIdx.x * 64, n0 = blockIdx.y * 64;
    const int tm = tid >> 4, tn = tid & 15;
    u64 acc[4][4] = {};
    const int ak0 = tid >> 5,         am0 = tid & 31;
    const int ak1 = (tid + 256) >> 5, am1 = am0;
    const int bk = tid >> 4, bn = (tid & 15) << 2;

    for (int k0 = 0; k0 < KTOT; k0 += 16) {
        float4 a0  = *(const float4*)&g_T[(k0 + ak0) * 256 + m0 + am0 * 2];
        float4 a1  = *(const float4*)&g_T[(k0 + ak1) * 256 + m0 + am1 * 2];
        float4 b1v = *(const float4*)&B1[(size_t)(k0 + bk) * 8192 + n0 + bn];
        float4 b2v = *(const float4*)&B2[(size_t)(k0 + bk) * 8192 + n0 + bn];
        __syncthreads();
        *(float4*)&As[ak0][am0 * 2] = a0;
        *(float4*)&As[ak1][am1 * 2] = a1;
        *(float4*)&Bs[bk][bn]     = make_float4(b1v.x, b2v.x, b1v.y, b2v.y);
        *(float4*)&Bs[bk][bn + 2] = make_float4(b1v.z, b2v.z, b1v.w, b2v.w);
        __syncthreads();
        #pragma unroll
        for (int kk = 0; kk < 16; kk++) {
            ulonglong2 a01 = *(const ulonglong2*)&As[kk][tm * 4];
            ulonglong2 a23 = *(const ulonglong2*)&As[kk][tm * 4 + 2];
            ulonglong2 b01 = *(const ulonglong2*)&Bs[kk][tn * 4];
            ulonglong2 b23 = *(const ulonglong2*)&Bs[kk][tn * 4 + 2];
            u64 av[4] = {a01.x, a01.y, a23.x, a23.y};
            u64 bv[4] = {b01.x, b01.y, b23.x, b23.y};
            #pragma unroll
            for (int i = 0; i < 4; i++) {
                #pragma unroll
                for (int j = 0; j < 4; j++) {
                    FMA2(acc[i][j], av[i], bv[j]);
                }
            }
        }
    }

    float cr[4][4], ci[4][4];
    #pragma unroll
    for (int i = 0; i < 4; i++)
        #pragma unroll
        for (int j = 0; j < 4; j++) upk2(acc[i][j], cr[i][j], ci[i][j]);

    if (MODE == 0) {
        #pragma unroll
        for (int i = 0; i < 4; i++) {
            int m = m0 + tm * 4 + i;
            size_t off = (size_t)m * 8192 + n0 + tn * 4;
            *(float4*)&g_Fr[off] = make_float4(cr[i][0], cr[i][1], cr[i][2], cr[i][3]);
            *(float4*)&g_Fi[off] = make_float4(ci[i][0], ci[i][1], ci[i][2], ci[i][3]);
        }
    } else {
        int n = n0 + tn * 4;
        int t = n >> 5, c = n & 31;
        #pragma unroll
        for (int i = 0; i < 4; i++) {
            int p = m0 + tm * 4 + i;
            float4 vp = make_float4(cr[i][0] + ci[i][0], cr[i][1] + ci[i][1],
                                    cr[i][2] + ci[i][2], cr[i][3] + ci[i][3]);
            *(float4*)&outp[((size_t)t * 511 + p) * 32 + c] = vp;
            if (p > 0) {
                float4 vm = make_float4(cr[i][0] - ci[i][0], cr[i][1] - ci[i][1],
                                        cr[i][2] - ci[i][2], cr[i][3] - ci[i][3]);
                *(float4*)&outp[((size_t)t * 511 + (511 - p)) * 32 + c] = vm;
            }
        }
    }
}

// ---------------- forward Legendre with f32x2 (pairs over l) ----------------
// flm[m][l][c] = sum_t P[m][l][t]*F[m][t][c]
__global__ void k_legfwd() {
    int lq = blockIdx.x, m = blockIdx.y;
    int c = threadIdx.x, lg = threadIdx.y;   // 32 x 8
    int tid = lg * 32 + c;
    int l0 = lq * 64;
    if (l0 + 63 < m) {
        for (int il = 0; il < 8; il++) {
            int l = l0 + lg * 8 + il;
            g_fr[(m * 256 + l) * 32 + c] = 0.f;
            g_fi[(m * 256 + l) * 32 + c] = 0.f;
        }
        return;
    }
    __shared__ __align__(16) float  Ps2[32 * 66];  // [tt][ll], stride 66 (8B-aligned pairs)
    __shared__ __align__(16) float2 Fs[32 * 32];   // [tt][c] = (fr, fi)
    u64 accr[4] = {}, acci[4] = {};
    for (int tch = 0; tch < 8; tch++) {
        int tb = tch * 32;
        for (int k = 0; k < 8; k++) {
            int i = tid + k * 256;
            int ll = i >> 5, tt = i & 31;      // coalesced g_P read over tt
            Ps2[tt * 66 + ll] = g_P[(m * 256 + (l0 + ll)) * 256 + tb + tt];
        }
        for (int k = 0; k < 4; k++) {
            int i = tid + k * 256;
            int tl = i >> 5, cc = i & 31;
            Fs[i] = make_float2(g_Fr[(m * 256 + tb + tl) * 32 + cc],
                                g_Fi[(m * 256 + tb + tl) * 32 + cc]);
        }
        __syncthreads();
        for (int tt = 0; tt < 32; tt++) {
            float2 f = Fs[tt * 32 + c];
            u64 frr = pk2(f.x, f.x), fii = pk2(f.y, f.y);
            const float* prow = &Ps2[tt * 66 + lg * 8];
            #pragma unroll
            for (int q = 0; q < 4; q++) {
                u64 pp = *(const u64*)(prow + 2 * q);  // (p_{2q}, p_{2q+1})
                FMA2(accr[q], pp, frr);
                FMA2(acci[q], pp, fii);
            }
        }
        __syncthreads();
    }
    #pragma unroll
    for (int q = 0; q < 4; q++) {
        float r0, r1, i0, i1;
        upk2(accr[q], r0, r1);
        upk2(acci[q], i0, i1);
        int l = l0 + lg * 8 + 2 * q;
        g_fr[(m * 256 + l) * 32 + c]       = r0;
        g_fi[(m * 256 + l) * 32 + c]       = i0;
        g_fr[(m * 256 + l + 1) * 32 + c]   = r1;
        g_fi[(m * 256 + l + 1) * 32 + c]   = i1;
    }
}

// ---------------- time embedding + weight modulation (merged) ----------------
__global__ void k_tcwmod(const float* __restrict__ t_emb,
                         const float* __restrict__ w_tr, const float* __restrict__ b_tr,
                         const float* __restrict__ w_ti, const float* __restrict__ b_ti,
                         const float* __restrict__ wr_in, const float* __restrict__ wi_in) {
    int l = blockIdx.x;           // 0..127
    int tid = threadIdx.x;        // 256
    int lane = tid & 31, wid = tid >> 5;
    __shared__ float sr[8], si[8];
    __shared__ float2 s_tc;
    float e = t_emb[tid];
    float pr = e * w_tr[tid * 128 + l];
    float pi = e * w_ti[tid * 128 + l];
    #pragma unroll
    for (int off = 16; off; off >>= 1) {
        pr += __shfl_down_sync(0xffffffffu, pr, off);
        pi += __shfl_down_sync(0xffffffffu, pi, off);
    }
    if (lane == 0) { sr[wid] = pr; si[wid] = pi; }
    __syncthreads();
    if (tid == 0) {
        float tr = b_tr[l], ti = b_ti[l];
        for (int w = 0; w < 8; w++) { tr += sr[w]; ti += si[w]; }
        s_tc = make_float2(tr, ti);
    }
    __syncthreads();
    float2 tc = s_tc;
    #pragma unroll
    for (int k = 0; k < 4; k++) {
        int io = tid + k * 256;
        float wr = wr_in[l * 1024 + io], wi = wi_in[l * 1024 + io];
        g_Wr[l * 1024 + io] = tc.x * wr - tc.y * wi;
        g_Wi[l * 1024 + io] = tc.x * wi + tc.y * wr;
    }
}

// ---------------- bilinear (antialiased) resize (256,511)->(128,255) ----------------
__global__ void k_resize() {
    int mo = blockIdx.x;   // 0..254
    int lo = blockIdx.y;   // 0..127
    int c  = threadIdx.x;  // 0..31

    float sfl = 2.f * lo + 0.5f;
    int jl0 = 2 * lo - 1;
    float wl[4]; float suml = 0.f;
    #pragma unroll
    for (int k = 0; k < 4; k++) {
        int j = jl0 + k;
        float wv = 0.f;
        if (j >= 0 && j < 256) {
            float d = fabsf(sfl - (float)j) * 0.5f;
            wv = fmaxf(0.f, 1.f - d);
        }
        wl[k] = wv; suml += wv;
    }
    #pragma unroll
    for (int k = 0; k < 4; k++) wl[k] /= suml;

    const float ks = 511.f / 255.f;
    float sfm = ((float)mo + 0.5f) * ks - 0.5f;
    int jm0 = (int)ceilf(sfm - ks);  if (jm0 < 0)   jm0 = 0;
    int jm1 = (int)floorf(sfm + ks); if (jm1 > 510) jm1 = 510;
    int nm = jm1 - jm0 + 1;
    float wm[6]; float summ = 0.f;
    for (int k = 0; k < nm; k++) {
        float d = fabsf(sfm - (float)(jm0 + k)) / ks;
        float wv = fmaxf(0.f, 1.f - d);
        wm[k] = wv; summ += wv;
    }
    for (int k = 0; k < nm; k++) wm[k] /= summ;

    float ar = 0.f, ai = 0.f;
    for (int kl = 0; kl < 4; kl++) {
        if (wl[kl] == 0.f) continue;
        int jl = jl0 + kl;
        for (int km = 0; km < nm; km++) {
            float wgt = wl[kl] * wm[km];
            int jm = jm0 + km;
            float r, i2;
            if (jm >= 255) {
                int mm = jm - 255;
                r  = g_fr[(mm * 256 + jl) * 32 + c];
                i2 = g_fi[(mm * 256 + jl) * 32 + c];
            } else {
                int mm = 255 - jm;
                float s = (mm & 1) ? -1.f : 1.f;
                r  =  s * g_fr[(mm * 256 + jl) * 32 + c];
                i2 = -s * g_fi[(mm * 256 + jl) * 32 + c];
            }
            ar += wgt * r; ai += wgt * i2;
        }
    }
    g_Ar[(lo * 255 + mo) * 32 + c] = ar;
    g_Ai[(lo * 255 + mo) * 32 + c] = ai;
}

// ---------------- per-l complex channel mix ----------------
__global__ void k_conv() {
    int l = blockIdx.x;
    int tid = threadIdx.x;           // 256
    int o = tid & 31, mg = tid >> 5;
    __shared__ float Wrs[1024], Wis[1024], Ars[256], Ais[256];
    for (int k = 0; k < 4; k++) {
        Wrs[tid + k * 256] = g_Wr[l * 1024 + tid + k * 256];
        Wis[tid + k * 256] = g_Wi[l * 1024 + tid + k * 256];
    }
    __syncthreads();
    for (int mb = 0; mb < 255; mb += 8) {
        int r = tid >> 5, cc = tid & 31;
        int mm = mb + r;
        if (mm < 255) {
            Ars[tid] = g_Ar[(l * 255 + mm) * 32 + cc];
            Ais[tid] = g_Ai[(l * 255 + mm) * 32 + cc];
        }
        __syncthreads();
        int mi = mb + mg;
        if (mi < 255) {
            float accr = 0.f, acci = 0.f;
            #pragma unroll
            for (int i = 0; i < 32; i++) {
                float ar = Ars[mg * 32 + i], ai = Ais[mg * 32 + i];
                float wr = Wrs[i * 32 + o],  wi = Wis[i * 32 + o];
                accr += ar * wr - ai * wi;
                acci += ar * wi + ai * wr;
            }
            g_Br[(mi * 128 + l) * 32 + o] = accr;
            g_Bi[(mi * 128 + l) * 32 + o] = acci;
        }
        __syncthreads();
    }
}

// ---------------- inverse Legendre with f32x2 (pairs over t) ----------------
// G[mi][t][c] = sum_{l<128} B[mi][l][c]*sgn*P[|m|][l][t]
__global__ void k_leginv() {
    int tq = blockIdx.x, mi = blockIdx.y;
    int c = threadIdx.x, tg = threadIdx.y;
    int tid = tg * 32 + c;
    int m = mi - 127;
    int mabs = m < 0 ? -m : m;
    float s = (m < 0 && (mabs & 1)) ? -1.f : 1.f;
    int t0 = tq * 64;
    __shared__ __align__(16) float  Ps[32 * 64];   // [ll][tt]
    __shared__ __align__(16) float2 Bsp[32 * 32];  // [ll][c] = (br, bi)
    u64 accr[4] = {}, acci[4] = {};
    for (int lc = 0; lc < 4; lc++) {
        int lb = lc * 32;
        for (int k = 0; k < 8; k++) {
            int i = tid + k * 256;
            int ll = i >> 6, tt = i & 63;
            Ps[i] = g_P[(mabs * 256 + lb + ll) * 256 + t0 + tt];
        }
        for (int k = 0; k < 4; k++) {
            int i = tid + k * 256;
            int ll = i >> 5, cc = i & 31;
            Bsp[i] = make_float2(s * g_Br[(mi * 128 + lb + ll) * 32 + cc],
                                 s * g_Bi[(mi * 128 + lb + ll) * 32 + cc]);
        }
        __syncthreads();
        for (int ll = 0; ll < 32; ll++) {
            float2 b = Bsp[ll * 32 + c];
            u64 brr = pk2(b.x, b.x), bii = pk2(b.y, b.y);
            const float* prow = &Ps[ll * 64 + tg * 8];
            #pragma unroll
            for (int q = 0; q < 4; q++) {
                u64 pp = *(const u64*)(prow + 2 * q);  // (p_{2q}, p_{2q+1})
                FMA2(accr[q], pp, brr);
                FMA2(acci[q], pp, bii);
            }
        }
        __syncthreads();
    }
    #pragma unroll
    for (int q = 0; q < 4; q++) {
        float r0, r1, i0, i1;
        upk2(accr[q], r0, r1);
        upk2(acci[q], i0, i1);
        int t = t0 + tg * 8 + 2 * q;
        g_Gr[((size_t)mi * 256 + t) * 32 + c]     = r0;
        g_Gi[((size_t)mi * 256 + t) * 32 + c]     = i0;
        g_Gr[((size_t)mi * 256 + t + 1) * 32 + c] = r1;
        g_Gi[((size_t)mi * 256 + t + 1) * 32 + c] = i1;
    }
}

// ---------------- fold G over +/-m ----------------
__global__ void k_fold2() {
    int mu = blockIdx.y;              // 0..127
    int tid = threadIdx.x;
    int t = blockIdx.x * 8 + (tid >> 5);
    int c = tid & 31;
    size_t tc = (size_t)t * 32 + c;
    float hc, hs;
    float grp = g_Gr[(size_t)(127 + mu) * 8192 + tc];
    float gip = g_Gi[(size_t)(127 + mu) * 8192 + tc];
    if (mu == 0) { hc = grp; hs = 0.f; }
    else {
        float grm = g_Gr[(size_t)(127 - mu) * 8192 + tc];
        float gim = g_Gi[(size_t)(127 - mu) * 8192 + tc];
        hc = grp + grm;
        hs = gim - gip;
    }
    g_Hc[(size_t)mu * 8192 + tc] = hc;
    g_Hs[(size_t)mu * 8192 + tc] = hs;
}

// ---------------- launch ----------------
extern "C" void kernel_launch(void* const* d_in, const int* in_sizes, int n_in,
                              void* d_out, int out_size) {
    const float* x     = (const float*)d_in[0];
    const float* t_emb = (const float*)d_in[1];
    const float* wr    = (const float*)d_in[2];
    const float* wi    = (const float*)d_in[3];
    const float* w_tr  = (const float*)d_in[4];
    const float* b_tr  = (const float*)d_in[5];
    const float* w_ti  = (const float*)d_in[6];
    const float* b_ti  = (const float*)d_in[7];
    float* out = (float*)d_out;

    k_coef<<<256, 256>>>();
    k_ttab<<<256, 256>>>();
    k_basis<<<256, 256>>>();
    k_tcwmod<<<128, 256>>>(t_emb, w_tr, b_tr, w_ti, b_ti, wr, wi);
    k_fold1<<<dim3(32, 256), 256>>>(x);
    k_gemm<256, 0><<<dim3(4, 128), 256>>>(nullptr);
    k_legfwd<<<dim3(4, 256), dim3(32, 8)>>>();
    k_resize<<<dim3(255, 128), 32>>>();
    k_conv<<<128, 256>>>();
    k_leginv<<<dim3(4, 255), dim3(32, 8)>>>();
    k_fold2<<<dim3(32, 128), 256>>>();
    k_gemm<128, 1><<<dim3(4, 128), 256>>>(out);
}

// round 8
// speedup vs baseline: 1.1199x; 1.1199x over previous
#include <cuda_runtime.h>
#include <math.h>

#define PI_D 3.14159265358979323846264338327950288

// Problem sizes: L=256, 2L-1=511, C=32, L_FREQ=128, MF=255, T_DIM=256

// ---------------- scratch (device globals; allocation-free) ----------------
__device__ float  g_P [16777216];              // [m][l][t]  256*256*256, zero for l<m
__device__ float  g_w [256];                   // quadrature weights sin(th)*dang^2
__device__ float  g_cs[256];                   // sqrt((2k+1)/(2k))
__device__ float2 g_ab[65536];                 // [m][l] recurrence coeffs (a,b)
__device__ __align__(16) float2 g_T[65536];    // [k][j] (cos,sin)(2*pi*k*j/511), k,j<256
__device__ __align__(16) float  g_xs[2097152]; // [p][t][c] folded+weighted x (sum)
__device__ __align__(16) float  g_xd[2097152]; // [p][t][c] folded+weighted x (diff)
__device__ __align__(16) float  g_Fr[2097152]; // [m][t][c]
__device__ __align__(16) float  g_Fi[2097152];
__device__ float  g_fr[2097152];               // [m][l][c] flm for m>=0
__device__ float  g_fi[2097152];
__device__ float  g_Ar[1044480];               // [lo][mo][c] resized flm
__device__ float  g_Ai[1044480];
__device__ float  g_Wr[131072];                // [l][i][o] modulated weight
__device__ float  g_Wi[131072];
__device__ float  g_Br[1044480];               // [mi][l][c] after channel mix
__device__ float  g_Bi[1044480];
__device__ float  g_Gr[2088960];               // [mi][t][c]
__device__ float  g_Gi[2088960];
__device__ __align__(16) float  g_Hc[1048576]; // [mu][t][c] m-folded cos coeff
__device__ __align__(16) float  g_Hs[1048576]; // [mu][t][c] m-folded sin coeff

// ---------------- recurrence coefficients (MUFU-heavy, tiny) ----------------
__global__ void k_coef() {
    int m = blockIdx.x, l = threadIdx.x;
    if (m == 0) {
        g_cs[l] = (l >= 1) ? sqrtf((2.f * l + 1.f) / (2.f * l)) : 0.f;
    }
    float2 ab = make_float2(0.f, 0.f);
    if (l >= m + 2) {
        float fl = (float)l, fm = (float)m;
        float denom = fl * fl - fm * fm;
        ab.x = sqrtf((4.f * fl * fl - 1.f) / denom);
        ab.y = sqrtf((2.f * fl + 1.f) * (fl - 1.f - fm) * (fl - 1.f + fm) /
                     ((2.f * fl - 3.f) * denom));
    }
    g_ab[m * 256 + l] = ab;
}

// ---------------- basis: pure-FMA recurrence using precomputed coeffs ----------------
__global__ void k_basis() {
    int m = blockIdx.x;
    int t = threadIdx.x;
    __shared__ float  cs[256];
    __shared__ float2 ab[256];
    cs[t] = g_cs[t];
    ab[t] = g_ab[m * 256 + t];
    double th = PI_D * (2.0 * t + 1.0) / 511.0;
    float ct = (float)cos(th), st = (float)sin(th);
    if (m == 0) {
        double dang = 2.0 * PI_D / 511.0;
        g_w[t] = (float)(sin(th) * dang * dang);
    }
    __syncthreads();
    float* Pm = g_P + m * 65536;
    for (int l = 0; l < m; l++) Pm[l * 256 + t] = 0.f;
    float pmm = 0.28209479177387814f;  // sqrt(1/(4*pi))
    for (int k = 1; k <= m; k++) pmm *= -cs[k] * st;
    Pm[m * 256 + t] = pmm;
    if (m + 1 < 256) {
        float pl1 = sqrtf(2.f * m + 3.f) * ct * pmm;
        Pm[(m + 1) * 256 + t] = pl1;
        float pl2 = pmm;
        for (int l = m + 2; l < 256; l++) {
            float2 c2 = ab[l];
            float p = c2.x * ct * pl1 - c2.y * pl2;
            Pm[l * 256 + t] = p;
            pl2 = pl1; pl1 = p;
        }
    }
}

// ---------------- twiddle table: (cos,sin)(2*pi*k*j/511), k,j in 0..255 ----------------
__global__ void k_ttab() {
    int k = blockIdx.x, j = threadIdx.x;
    int kj = (k * j) % 511;
    double s, c;
    sincos(2.0 * PI_D * (double)kj / 511.0, &s, &c);
    g_T[k * 256 + j] = make_float2((float)c, (float)s);
}

// ---------------- fold x over p-pairs, apply quadrature weight ----------------
__global__ void k_fold1(const float* __restrict__ x) {
    int p = blockIdx.y;
    int tid = threadIdx.x;
    int t = blockIdx.x * 8 + (tid >> 5);
    int c = tid & 31;
    float w = g_w[t];
    float a = x[((size_t)t * 511 + p) * 32 + c];
    float xs, xd;
    if (p == 0) { xs = w * a; xd = 0.f; }
    else {
        float b = x[((size_t)t * 511 + (511 - p)) * 32 + c];
        xs = w * (a + b);
        xd = w * (b - a);
    }
    size_t o = ((size_t)p * 256 + t) * 32 + c;
    g_xs[o] = xs;
    g_xd[o] = xd;
}

// ---------------- tiled dual-GEMM: Cr = cos^T * B1, Ci = sin^T * B2 ----------------
// MODE 0: B1=g_xs, B2=g_xd -> g_Fr, g_Fi (forward DFT)
// MODE 1: B1=g_Hc, B2=g_Hs -> out with p-fold epilogue
template<int KTOT, int MODE>
__global__ void __launch_bounds__(256)
k_gemm(float* __restrict__ outp) {
    const float* __restrict__ B1 = (MODE == 0) ? g_xs : g_Hc;
    const float* __restrict__ B2 = (MODE == 0) ? g_xd : g_Hs;
    __shared__ float2 As[16][64];
    __shared__ float  Bs1[16][64], Bs2[16][64];
    const int tid = threadIdx.x;
    const int m0 = blockIdx.x * 64, n0 = blockIdx.y * 64;
    const int tm = tid >> 4, tn = tid & 15;
    float cr[4][4] = {}, ci[4][4] = {};
    const int ak0 = tid >> 5,         am0 = tid & 31;
    const int ak1 = (tid + 256) >> 5, am1 = am0;
    const int bk = tid >> 4, bn = (tid & 15) << 2;

    for (int k0 = 0; k0 < KTOT; k0 += 16) {
        float4 a0  = *(const float4*)&g_T[(k0 + ak0) * 256 + m0 + am0 * 2];
        float4 a1  = *(const float4*)&g_T[(k0 + ak1) * 256 + m0 + am1 * 2];
        float4 b1v = *(const float4*)&B1[(size_t)(k0 + bk) * 8192 + n0 + bn];
        float4 b2v = *(const float4*)&B2[(size_t)(k0 + bk) * 8192 + n0 + bn];
        __syncthreads();
        *(float4*)&As[ak0][am0 * 2] = a0;
        *(float4*)&As[ak1][am1 * 2] = a1;
        *(float4*)&Bs1[bk][bn] = b1v;
        *(float4*)&Bs2[bk][bn] = b2v;
        __syncthreads();
        #pragma unroll
        for (int kk = 0; kk < 16; kk++) {
            float4 a01 = *(float4*)&As[kk][tm * 4];
            float4 a23 = *(float4*)&As[kk][tm * 4 + 2];
            float4 b1f = *(float4*)&Bs1[kk][tn * 4];
            float4 b2f = *(float4*)&Bs2[kk][tn * 4];
            float co[4] = {a01.x, a01.z, a23.x, a23.z};
            float si[4] = {a01.y, a01.w, a23.y, a23.w};
            float u1[4] = {b1f.x, b1f.y, b1f.z, b1f.w};
            float u2[4] = {b2f.x, b2f.y, b2f.z, b2f.w};
            #pragma unroll
            for (int i = 0; i < 4; i++) {
                #pragma unroll
                for (int j = 0; j < 4; j++) {
                    cr[i][j] += co[i] * u1[j];
                    ci[i][j] += si[i] * u2[j];
                }
            }
        }
    }

    if (MODE == 0) {
        #pragma unroll
        for (int i = 0; i < 4; i++) {
            int m = m0 + tm * 4 + i;
            size_t off = (size_t)m * 8192 + n0 + tn * 4;
            *(float4*)&g_Fr[off] = make_float4(cr[i][0], cr[i][1], cr[i][2], cr[i][3]);
            *(float4*)&g_Fi[off] = make_float4(ci[i][0], ci[i][1], ci[i][2], ci[i][3]);
        }
    } else {
        int n = n0 + tn * 4;
        int t = n >> 5, c = n & 31;
        #pragma unroll
        for (int i = 0; i < 4; i++) {
            int p = m0 + tm * 4 + i;
            float4 vp = make_float4(cr[i][0] + ci[i][0], cr[i][1] + ci[i][1],
                                    cr[i][2] + ci[i][2], cr[i][3] + ci[i][3]);
            *(float4*)&outp[((size_t)t * 511 + p) * 32 + c] = vp;
            if (p > 0) {
                float4 vm = make_float4(cr[i][0] - ci[i][0], cr[i][1] - ci[i][1],
                                        cr[i][2] - ci[i][2], cr[i][3] - ci[i][3]);
                *(float4*)&outp[((size_t)t * 511 + (511 - p)) * 32 + c] = vm;
            }
        }
    }
}

// ---------------- forward Legendre: flm[m][l][c] = sum_t P[m][l][t]*F[m][t][c] ----------------
__global__ void k_legfwd() {
    int lq = blockIdx.x, m = blockIdx.y;
    int c = threadIdx.x, lg = threadIdx.y;
    int tid = lg * 32 + c;
    int l0 = lq * 64;
    if (l0 + 63 < m) {
        for (int il = 0; il < 8; il++) {
            int l = l0 + lg * 8 + il;
            g_fr[(m * 256 + l) * 32 + c] = 0.f;
            g_fi[(m * 256 + l) * 32 + c] = 0.f;
        }
        return;
    }
    __shared__ float Ps[64 * 32];
    __shared__ float Frs[32 * 32];
    __shared__ float Fis[32 * 32];
    float accr[8], acci[8];
    #pragma unroll
    for (int il = 0; il < 8; il++) { accr[il] = 0.f; acci[il] = 0.f; }
    for (int tch = 0; tch < 8; tch++) {
        int tb = tch * 32;
        for (int k = 0; k < 8; k++) {
            int i = tid + k * 256;
            int ll = i >> 5, tt = i & 31;
            Ps[i] = g_P[(m * 256 + (l0 + ll)) * 256 + tb + tt];
        }
        for (int k = 0; k < 4; k++) {
            int i = tid + k * 256;
            int tl = i >> 5, cc = i & 31;
            Frs[i] = g_Fr[(m * 256 + tb + tl) * 32 + cc];
            Fis[i] = g_Fi[(m * 256 + tb + tl) * 32 + cc];
        }
        __syncthreads();
        for (int tt = 0; tt < 32; tt++) {
            float fr = Frs[tt * 32 + c], fi = Fis[tt * 32 + c];
            #pragma unroll
            for (int il = 0; il < 8; il++) {
                float p = Ps[(lg * 8 + il) * 32 + tt];
                accr[il] += p * fr;
                acci[il] += p * fi;
            }
        }
        __syncthreads();
    }
    for (int il = 0; il < 8; il++) {
        int l = l0 + lg * 8 + il;
        g_fr[(m * 256 + l) * 32 + c] = accr[il];
        g_fi[(m * 256 + l) * 32 + c] = acci[il];
    }
}

// ---------------- time embedding + weight modulation (merged) ----------------
__global__ void k_tcwmod(const float* __restrict__ t_emb,
                         const float* __restrict__ w_tr, const float* __restrict__ b_tr,
                         const float* __restrict__ w_ti, const float* __restrict__ b_ti,
                         const float* __restrict__ wr_in, const float* __restrict__ wi_in) {
    int l = blockIdx.x;           // 0..127
    int tid = threadIdx.x;        // 256
    int lane = tid & 31, wid = tid >> 5;
    __shared__ float sr[8], si[8];
    __shared__ float2 s_tc;
    float e = t_emb[tid];
    float pr = e * w_tr[tid * 128 + l];
    float pi = e * w_ti[tid * 128 + l];
    #pragma unroll
    for (int off = 16; off; off >>= 1) {
        pr += __shfl_down_sync(0xffffffffu, pr, off);
        pi += __shfl_down_sync(0xffffffffu, pi, off);
    }
    if (lane == 0) { sr[wid] = pr; si[wid] = pi; }
    __syncthreads();
    if (tid == 0) {
        float tr = b_tr[l], ti = b_ti[l];
        for (int w = 0; w < 8; w++) { tr += sr[w]; ti += si[w]; }
        s_tc = make_float2(tr, ti);
    }
    __syncthreads();
    float2 tc = s_tc;
    #pragma unroll
    for (int k = 0; k < 4; k++) {
        int io = tid + k * 256;
        float wr = wr_in[l * 1024 + io], wi = wi_in[l * 1024 + io];
        g_Wr[l * 1024 + io] = tc.x * wr - tc.y * wi;
        g_Wi[l * 1024 + io] = tc.x * wi + tc.y * wr;
    }
}

// ---------------- bilinear (antialiased) resize (256,511)->(128,255) ----------------
__global__ void k_resize() {
    int mo = blockIdx.x;   // 0..254
    int lo = blockIdx.y;   // 0..127
    int c  = threadIdx.x;  // 0..31

    float sfl = 2.f * lo + 0.5f;
    int jl0 = 2 * lo - 1;
    float wl[4]; float suml = 0.f;
    #pragma unroll
    for (int k = 0; k < 4; k++) {
        int j = jl0 + k;
        float wv = 0.f;
        if (j >= 0 && j < 256) {
            float d = fabsf(sfl - (float)j) * 0.5f;
            wv = fmaxf(0.f, 1.f - d);
        }
        wl[k] = wv; suml += wv;
    }
    #pragma unroll
    for (int k = 0; k < 4; k++) wl[k] /= suml;

    const float ks = 511.f / 255.f;
    float sfm = ((float)mo + 0.5f) * ks - 0.5f;
    int jm0 = (int)ceilf(sfm - ks);  if (jm0 < 0)   jm0 = 0;
    int jm1 = (int)floorf(sfm + ks); if (jm1 > 510) jm1 = 510;
    int nm = jm1 - jm0 + 1;
    float wm[6]; float summ = 0.f;
    for (int k = 0; k < nm; k++) {
        float d = fabsf(sfm - (float)(jm0 + k)) / ks;
        float wv = fmaxf(0.f, 1.f - d);
        wm[k] = wv; summ += wv;
    }
    for (int k = 0; k < nm; k++) wm[k] /= summ;

    float ar = 0.f, ai = 0.f;
    for (int kl = 0; kl < 4; kl++) {
        if (wl[kl] == 0.f) continue;
        int jl = jl0 + kl;
        for (int km = 0; km < nm; km++) {
            float wgt = wl[kl] * wm[km];
            int jm = jm0 + km;
            float r, i2;
            if (jm >= 255) {
                int mm = jm - 255;
                r  = g_fr[(mm * 256 + jl) * 32 + c];
                i2 = g_fi[(mm * 256 + jl) * 32 + c];
            } else {
                int mm = 255 - jm;
                float s = (mm & 1) ? -1.f : 1.f;
                r  =  s * g_fr[(mm * 256 + jl) * 32 + c];
                i2 = -s * g_fi[(mm * 256 + jl) * 32 + c];
            }
            ar += wgt * r; ai += wgt * i2;
        }
    }
    g_Ar[(lo * 255 + mo) * 32 + c] = ar;
    g_Ai[(lo * 255 + mo) * 32 + c] = ai;
}

// ---------------- per-l complex channel mix ----------------
__global__ void k_conv() {
    int l = blockIdx.x;
    int tid = threadIdx.x;           // 256
    int o = tid & 31, mg = tid >> 5;
    __shared__ float Wrs[1024], Wis[1024], Ars[256], Ais[256];
    for (int k = 0; k < 4; k++) {
        Wrs[tid + k * 256] = g_Wr[l * 1024 + tid + k * 256];
        Wis[tid + k * 256] = g_Wi[l * 1024 + tid + k * 256];
    }
    __syncthreads();
    for (int mb = 0; mb < 255; mb += 8) {
        int r = tid >> 5, cc = tid & 31;
        int mm = mb + r;
        if (mm < 255) {
            Ars[tid] = g_Ar[(l * 255 + mm) * 32 + cc];
            Ais[tid] = g_Ai[(l * 255 + mm) * 32 + cc];
        }
        __syncthreads();
        int mi = mb + mg;
        if (mi < 255) {
            float accr = 0.f, acci = 0.f;
            #pragma unroll
            for (int i = 0; i < 32; i++) {
                float ar = Ars[mg * 32 + i], ai = Ais[mg * 32 + i];
                float wr = Wrs[i * 32 + o],  wi = Wis[i * 32 + o];
                accr += ar * wr - ai * wi;
                acci += ar * wi + ai * wr;
            }
            g_Br[(mi * 128 + l) * 32 + o] = accr;
            g_Bi[(mi * 128 + l) * 32 + o] = acci;
        }
        __syncthreads();
    }
}

// ---------------- inverse Legendre: G[mi][t][c] = sum_{l<128} B[mi][l][c]*sgn*P[|m|][l][t] ----------------
// l-chunks with lb+31 < |m| are exactly zero (P[|m|][l]=0 for l<|m|) -> skipped.
__global__ void k_leginv() {
    int tq = blockIdx.x, mi = blockIdx.y;
    int c = threadIdx.x, tg = threadIdx.y;
    int tid = tg * 32 + c;
    int m = mi - 127;
    int mabs = m < 0 ? -m : m;
    float s = (m < 0 && (mabs & 1)) ? -1.f : 1.f;
    int t0 = tq * 64;
    __shared__ float Ps[32 * 64], Brs[32 * 32], Bis[32 * 32];
    float accr[8], acci[8];
    #pragma unroll
    for (int k = 0; k < 8; k++) { accr[k] = 0.f; acci[k] = 0.f; }
    int lc0 = mabs >> 5;   // first chunk with any nonzero P rows (block-uniform)
    for (int lc = lc0; lc < 4; lc++) {
        int lb = lc * 32;
        for (int k = 0; k < 8; k++) {
            int i = tid + k * 256;
            int ll = i >> 6, tt = i & 63;
            Ps[i] = g_P[(mabs * 256 + lb + ll) * 256 + t0 + tt];
        }
        for (int k = 0; k < 4; k++) {
            int i = tid + k * 256;
            int ll = i >> 5, cc = i & 31;
            Brs[i] = s * g_Br[(mi * 128 + lb + ll) * 32 + cc];
            Bis[i] = s * g_Bi[(mi * 128 + lb + ll) * 32 + cc];
        }
        __syncthreads();
        for (int ll = 0; ll < 32; ll++) {
            float br = Brs[ll * 32 + c], bi = Bis[ll * 32 + c];
            #pragma unroll
            for (int k = 0; k < 8; k++) {
                float p = Ps[ll * 64 + tg * 8 + k];
                accr[k] += br * p;
                acci[k] += bi * p;
            }
        }
        __syncthreads();
    }
    for (int k = 0; k < 8; k++) {
        int t = t0 + tg * 8 + k;
        g_Gr[((size_t)mi * 256 + t) * 32 + c] = accr[k];
        g_Gi[((size_t)mi * 256 + t) * 32 + c] = acci[k];
    }
}

// ---------------- fold G over +/-m ----------------
__global__ void k_fold2() {
    int mu = blockIdx.y;              // 0..127
    int tid = threadIdx.x;
    int t = blockIdx.x * 8 + (tid >> 5);
    int c = tid & 31;
    size_t tc = (size_t)t * 32 + c;
    float hc, hs;
    float grp = g_Gr[(size_t)(127 + mu) * 8192 + tc];
    float gip = g_Gi[(size_t)(127 + mu) * 8192 + tc];
    if (mu == 0) { hc = grp; hs = 0.f; }
    else {
        float grm = g_Gr[(size_t)(127 - mu) * 8192 + tc];
        float gim = g_Gi[(size_t)(127 - mu) * 8192 + tc];
        hc = grp + grm;
        hs = gim - gip;
    }
    g_Hc[(size_t)mu * 8192 + tc] = hc;
    g_Hs[(size_t)mu * 8192 + tc] = hs;
}

// ---------------- launch ----------------
extern "C" void kernel_launch(void* const* d_in, const int* in_sizes, int n_in,
                              void* d_out, int out_size) {
    const float* x     = (const float*)d_in[0];
    const float* t_emb = (const float*)d_in[1];
    const float* wr    = (const float*)d_in[2];
    const float* wi    = (const float*)d_in[3];
    const float* w_tr  = (const float*)d_in[4];
    const float* b_tr  = (const float*)d_in[5];
    const float* w_ti  = (const float*)d_in[6];
    const float* b_ti  = (const float*)d_in[7];
    float* out = (float*)d_out;

    k_coef<<<256, 256>>>();
    k_ttab<<<256, 256>>>();
    k_basis<<<256, 256>>>();
    k_tcwmod<<<128, 256>>>(t_emb, w_tr, b_tr, w_ti, b_ti, wr, wi);
    k_fold1<<<dim3(32, 256), 256>>>(x);
    k_gemm<256, 0><<<dim3(4, 128), 256>>>(nullptr);
    k_legfwd<<<dim3(4, 256), dim3(32, 8)>>>();
    k_resize<<<dim3(255, 128), 32>>>();
    k_conv<<<128, 256>>>();
    k_leginv<<<dim3(4, 255), dim3(32, 8)>>>();
    k_fold2<<<dim3(32, 128), 256>>>();
    k_gemm<128, 1><<<dim3(4, 128), 256>>>(out);
}

// round 9
// speedup vs baseline: 1.3231x; 1.1814x over previous
#include <cuda_runtime.h>
#include <math.h>

#define PI_D 3.14159265358979323846264338327950288

// Problem sizes: L=256, 2L-1=511, C=32, L_FREQ=128, MF=255, T_DIM=256

__device__ __forceinline__ float tf32r(float x) {
    float y; asm("cvt.rna.tf32.f32 %0, %1;" : "=f"(y) : "f"(x)); return y;
}

#define MMA_TF32(C, A, b0, b1)                                                  \
    asm volatile("mma.sync.aligned.m16n8k8.row.col.f32.tf32.tf32.f32 "          \
                 "{%0,%1,%2,%3}, {%4,%5,%6,%7}, {%8,%9}, {%0,%1,%2,%3};"        \
                 : "+f"(C[0]), "+f"(C[1]), "+f"(C[2]), "+f"(C[3])               \
                 : "r"(A[0]), "r"(A[1]), "r"(A[2]), "r"(A[3]), "r"(b0), "r"(b1))

// ---------------- scratch (device globals; allocation-free) ----------------
__device__ float  g_P [16777216];              // [m][l][t]  256*256*256, zero for l<m
__device__ float  g_w [256];                   // quadrature weights sin(th)*dang^2
__device__ float  g_cs[256];                   // sqrt((2k+1)/(2k))
__device__ float2 g_ab[65536];                 // [m][l] recurrence coeffs (a,b)
__device__ __align__(16) float2 g_T[65536];    // [k][j] tf32-rounded (cos,sin)(2*pi*k*j/511)
__device__ __align__(16) float  g_xs[2097152]; // [p][t][c] folded+weighted x (sum), tf32
__device__ __align__(16) float  g_xd[2097152]; // [p][t][c] folded+weighted x (diff), tf32
__device__ __align__(16) float  g_Fr[2097152]; // [m][t][c]
__device__ __align__(16) float  g_Fi[2097152];
__device__ float  g_fr[2097152];               // [m][l][c] flm for m>=0
__device__ float  g_fi[2097152];
__device__ float  g_Ar[1044480];               // [lo][mo][c] resized flm
__device__ float  g_Ai[1044480];
__device__ float  g_Wr[131072];                // [l][i][o] modulated weight
__device__ float  g_Wi[131072];
__device__ float  g_Br[1044480];               // [mi][l][c] after channel mix
__device__ float  g_Bi[1044480];
__device__ float  g_Gr[2088960];               // [mi][t][c]
__device__ float  g_Gi[2088960];
__device__ __align__(16) float  g_Hc[1048576]; // [mu][t][c] m-folded cos coeff, tf32
__device__ __align__(16) float  g_Hs[1048576]; // [mu][t][c] m-folded sin coeff, tf32

// ---------------- recurrence coefficients + quadrature weights ----------------
__global__ void k_coef() {
    int m = blockIdx.x, l = threadIdx.x;
    if (m == 0) {
        g_cs[l] = (l >= 1) ? sqrtf((2.f * l + 1.f) / (2.f * l)) : 0.f;
        double th = PI_D * (2.0 * l + 1.0) / 511.0;
        double dang = 2.0 * PI_D / 511.0;
        g_w[l] = (float)(sin(th) * dang * dang);
    }
    float2 ab = make_float2(0.f, 0.f);
    if (l >= m + 2) {
        float fl = (float)l, fm = (float)m;
        float denom = fl * fl - fm * fm;
        ab.x = sqrtf((4.f * fl * fl - 1.f) / denom);
        ab.y = sqrtf((2.f * fl + 1.f) * (fl - 1.f - fm) * (fl - 1.f + fm) /
                     ((2.f * fl - 3.f) * denom));
    }
    g_ab[m * 256 + l] = ab;
}

// ---------------- twiddle table (tf32-rounded) ----------------
__global__ void k_ttab() {
    int k = blockIdx.x, j = threadIdx.x;
    int kj = (k * j) % 511;
    double s, c;
    sincos(2.0 * PI_D * (double)kj / 511.0, &s, &c);
    g_T[k * 256 + j] = make_float2(tf32r((float)c), tf32r((float)s));
}

// ---------------- fold x over p-pairs, apply quadrature weight (tf32-rounded) ----------------
__global__ void k_fold1(const float* __restrict__ x) {
    int p = blockIdx.y;
    int tid = threadIdx.x;
    int t = blockIdx.x * 8 + (tid >> 5);
    int c = tid & 31;
    float w = g_w[t];
    float a = x[((size_t)t * 511 + p) * 32 + c];
    float xs, xd;
    if (p == 0) { xs = w * a; xd = 0.f; }
    else {
        float b = x[((size_t)t * 511 + (511 - p)) * 32 + c];
        xs = w * (a + b);
        xd = w * (b - a);
    }
    size_t o = ((size_t)p * 256 + t) * 32 + c;
    g_xs[o] = tf32r(xs);
    g_xd[o] = tf32r(xd);
}

// ---------------- tf32 tensor-core dual-GEMM ----------------
// Cr[m][n] = sum_k cosT[k][m]*B1[k][n];  Ci[m][n] = sum_k sinT[k][m]*B2[k][n]
// MODE 0: B1=g_xs, B2=g_xd -> g_Fr=Cr, g_Fi=Ci  (forward DFT)
// MODE 1: B1=g_Hc, B2=g_Hs -> out[t][p][c]=Cr+Ci, out[t][511-p][c]=Cr-Ci
// Block tile M=64, N=64, K-chunk 32. 8 warps as 4(M) x 2(N); warp tile 16x32.
template<int KTOT, int MODE>
__global__ void __launch_bounds__(256)
k_gemm(float* __restrict__ outp) {
    const float* __restrict__ B1 = (MODE == 0) ? g_xs : g_Hc;
    const float* __restrict__ B2 = (MODE == 0) ? g_xd : g_Hs;
    __shared__ float2 Asm[32][66];     // [k][m] (cos,sin)
    __shared__ float  Bsm1[32][68];    // [k][n]
    __shared__ float  Bsm2[32][68];
    const int tid = threadIdx.x;
    const int w = tid >> 5, lane = tid & 31;
    const int g = lane >> 2, t4 = lane & 3;
    const int m0 = blockIdx.x * 64, n0 = blockIdx.y * 64;
    const int warpM = (w >> 1) * 16, warpN = (w & 1) * 32;
    float cr[4][4] = {}, ci[4][4] = {};

    for (int k0 = 0; k0 < KTOT; k0 += 32) {
        __syncthreads();
        // A tile: 32 k-rows x 64 m-cols of float2
        #pragma unroll
        for (int p = 0; p < 8; p++) {
            int idx = p * 256 + tid;
            int kk = idx >> 6, mm = idx & 63;
            Asm[kk][mm] = g_T[(k0 + kk) * 256 + m0 + mm];
        }
        // B tiles: 32 k-rows x 64 n-cols
        #pragma unroll
        for (int p = 0; p < 2; p++) {
            int kk = p * 16 + (tid >> 4);
            int nn = (tid & 15) * 4;
            *(float4*)&Bsm1[kk][nn] = *(const float4*)&B1[(size_t)(k0 + kk) * 8192 + n0 + nn];
            *(float4*)&Bsm2[kk][nn] = *(const float4*)&B2[(size_t)(k0 + kk) * 8192 + n0 + nn];
        }
        __syncthreads();
        #pragma unroll
        for (int ks = 0; ks < 4; ks++) {
            int kb = ks * 8;
            float2 v00 = Asm[kb + t4][warpM + g];
            float2 v10 = Asm[kb + t4][warpM + g + 8];
            float2 v01 = Asm[kb + t4 + 4][warpM + g];
            float2 v11 = Asm[kb + t4 + 4][warpM + g + 8];
            unsigned ac[4] = {__float_as_uint(v00.x), __float_as_uint(v10.x),
                              __float_as_uint(v01.x), __float_as_uint(v11.x)};
            unsigned as[4] = {__float_as_uint(v00.y), __float_as_uint(v10.y),
                              __float_as_uint(v01.y), __float_as_uint(v11.y)};
            #pragma unroll
            for (int nb = 0; nb < 4; nb++) {
                int nc = warpN + nb * 8 + g;
                unsigned b1a = __float_as_uint(Bsm1[kb + t4][nc]);
                unsigned b1b = __float_as_uint(Bsm1[kb + t4 + 4][nc]);
                unsigned b2a = __float_as_uint(Bsm2[kb + t4][nc]);
                unsigned b2b = __float_as_uint(Bsm2[kb + t4 + 4][nc]);
                MMA_TF32(cr[nb], ac, b1a, b1b);
                MMA_TF32(ci[nb], as, b2a, b2b);
            }
        }
    }

    if (MODE == 0) {
        int m_row = m0 + warpM + g;
        #pragma unroll
        for (int nb = 0; nb < 4; nb++) {
            int n = n0 + warpN + nb * 8 + 2 * t4;
            size_t o0 = (size_t)m_row * 8192 + n;
            size_t o1 = (size_t)(m_row + 8) * 8192 + n;
            *(float2*)&g_Fr[o0] = make_float2(cr[nb][0], cr[nb][1]);
            *(float2*)&g_Fr[o1] = make_float2(cr[nb][2], cr[nb][3]);
            *(float2*)&g_Fi[o0] = make_float2(ci[nb][0], ci[nb][1]);
            *(float2*)&g_Fi[o1] = make_float2(ci[nb][2], ci[nb][3]);
        }
    } else {
        int p0r = m0 + warpM + g;
        int p1r = p0r + 8;
        #pragma unroll
        for (int nb = 0; nb < 4; nb++) {
            int n = n0 + warpN + nb * 8 + 2 * t4;
            int t = n >> 5, c = n & 31;
            float2 vp0 = make_float2(cr[nb][0] + ci[nb][0], cr[nb][1] + ci[nb][1]);
            *(float2*)&outp[((size_t)t * 511 + p0r) * 32 + c] = vp0;
            if (p0r > 0) {
                float2 vm0 = make_float2(cr[nb][0] - ci[nb][0], cr[nb][1] - ci[nb][1]);
                *(float2*)&outp[((size_t)t * 511 + (511 - p0r)) * 32 + c] = vm0;
            }
            float2 vp1 = make_float2(cr[nb][2] + ci[nb][2], cr[nb][3] + ci[nb][3]);
            *(float2*)&outp[((size_t)t * 511 + p1r) * 32 + c] = vp1;
            float2 vm1 = make_float2(cr[nb][2] - ci[nb][2], cr[nb][3] - ci[nb][3]);
            *(float2*)&outp[((size_t)t * 511 + (511 - p1r)) * 32 + c] = vm1;
        }
    }
}

// ---------------- basis: pure-FMA recurrence using precomputed coeffs ----------------
__global__ void k_basis() {
    int m = blockIdx.x;
    int t = threadIdx.x;
    __shared__ float  cs[256];
    __shared__ float2 ab[256];
    cs[t] = g_cs[t];
    ab[t] = g_ab[m * 256 + t];
    double th = PI_D * (2.0 * t + 1.0) / 511.0;
    float ct = (float)cos(th), st = (float)sin(th);
    __syncthreads();
    float* Pm = g_P + m * 65536;
    for (int l = 0; l < m; l++) Pm[l * 256 + t] = 0.f;
    float pmm = 0.28209479177387814f;  // sqrt(1/(4*pi))
    for (int k = 1; k <= m; k++) pmm *= -cs[k] * st;
    Pm[m * 256 + t] = pmm;
    if (m + 1 < 256) {
        float pl1 = sqrtf(2.f * m + 3.f) * ct * pmm;
        Pm[(m + 1) * 256 + t] = pl1;
        float pl2 = pmm;
        for (int l = m + 2; l < 256; l++) {
            float2 c2 = ab[l];
            float p = c2.x * ct * pl1 - c2.y * pl2;
            Pm[l * 256 + t] = p;
            pl2 = pl1; pl1 = p;
        }
    }
}

// ---------------- forward Legendre: flm[m][l][c] = sum_t P[m][l][t]*F[m][t][c] ----------------
__global__ void k_legfwd() {
    int lq = blockIdx.x, m = blockIdx.y;
    int c = threadIdx.x, lg = threadIdx.y;
    int tid = lg * 32 + c;
    int l0 = lq * 64;
    if (l0 + 63 < m) {
        for (int il = 0; il < 8; il++) {
            int l = l0 + lg * 8 + il;
            g_fr[(m * 256 + l) * 32 + c] = 0.f;
            g_fi[(m * 256 + l) * 32 + c] = 0.f;
        }
        return;
    }
    __shared__ float Ps[64 * 32];
    __shared__ float Frs[32 * 32];
    __shared__ float Fis[32 * 32];
    float accr[8], acci[8];
    #pragma unroll
    for (int il = 0; il < 8; il++) { accr[il] = 0.f; acci[il] = 0.f; }
    for (int tch = 0; tch < 8; tch++) {
        int tb = tch * 32;
        for (int k = 0; k < 8; k++) {
            int i = tid + k * 256;
            int ll = i >> 5, tt = i & 31;
            Ps[i] = g_P[(m * 256 + (l0 + ll)) * 256 + tb + tt];
        }
        for (int k = 0; k < 4; k++) {
            int i = tid + k * 256;
            int tl = i >> 5, cc = i & 31;
            Frs[i] = g_Fr[(m * 256 + tb + tl) * 32 + cc];
            Fis[i] = g_Fi[(m * 256 + tb + tl) * 32 + cc];
        }
        __syncthreads();
        for (int tt = 0; tt < 32; tt++) {
            float fr = Frs[tt * 32 + c], fi = Fis[tt * 32 + c];
            #pragma unroll
            for (int il = 0; il < 8; il++) {
                float p = Ps[(lg * 8 + il) * 32 + tt];
                accr[il] += p * fr;
                acci[il] += p * fi;
            }
        }
        __syncthreads();
    }
    for (int il = 0; il < 8; il++) {
        int l = l0 + lg * 8 + il;
        g_fr[(m * 256 + l) * 32 + c] = accr[il];
        g_fi[(m * 256 + l) * 32 + c] = acci[il];
    }
}

// ---------------- time embedding + weight modulation (merged) ----------------
__global__ void k_tcwmod(const float* __restrict__ t_emb,
                         const float* __restrict__ w_tr, const float* __restrict__ b_tr,
                         const float* __restrict__ w_ti, const float* __restrict__ b_ti,
                         const float* __restrict__ wr_in, const float* __restrict__ wi_in) {
    int l = blockIdx.x;           // 0..127
    int tid = threadIdx.x;        // 256
    int lane = tid & 31, wid = tid >> 5;
    __shared__ float sr[8], si[8];
    __shared__ float2 s_tc;
    float e = t_emb[tid];
    float pr = e * w_tr[tid * 128 + l];
    float pi = e * w_ti[tid * 128 + l];
    #pragma unroll
    for (int off = 16; off; off >>= 1) {
        pr += __shfl_down_sync(0xffffffffu, pr, off);
        pi += __shfl_down_sync(0xffffffffu, pi, off);
    }
    if (lane == 0) { sr[wid] = pr; si[wid] = pi; }
    __syncthreads();
    if (tid == 0) {
        float tr = b_tr[l], ti = b_ti[l];
        for (int w = 0; w < 8; w++) { tr += sr[w]; ti += si[w]; }
        s_tc = make_float2(tr, ti);
    }
    __syncthreads();
    float2 tc = s_tc;
    #pragma unroll
    for (int k = 0; k < 4; k++) {
        int io = tid + k * 256;
        float wr = wr_in[l * 1024 + io], wi = wi_in[l * 1024 + io];
        g_Wr[l * 1024 + io] = tc.x * wr - tc.y * wi;
        g_Wi[l * 1024 + io] = tc.x * wi + tc.y * wr;
    }
}

// ---------------- bilinear (antialiased) resize (256,511)->(128,255) ----------------
__global__ void k_resize() {
    int mo = blockIdx.x;   // 0..254
    int lo = blockIdx.y;   // 0..127
    int c  = threadIdx.x;  // 0..31

    float sfl = 2.f * lo + 0.5f;
    int jl0 = 2 * lo - 1;
    float wl[4]; float suml = 0.f;
    #pragma unroll
    for (int k = 0; k < 4; k++) {
        int j = jl0 + k;
        float wv = 0.f;
        if (j >= 0 && j < 256) {
            float d = fabsf(sfl - (float)j) * 0.5f;
            wv = fmaxf(0.f, 1.f - d);
        }
        wl[k] = wv; suml += wv;
    }
    #pragma unroll
    for (int k = 0; k < 4; k++) wl[k] /= suml;

    const float ks = 511.f / 255.f;
    float sfm = ((float)mo + 0.5f) * ks - 0.5f;
    int jm0 = (int)ceilf(sfm - ks);  if (jm0 < 0)   jm0 = 0;
    int jm1 = (int)floorf(sfm + ks); if (jm1 > 510) jm1 = 510;
    int nm = jm1 - jm0 + 1;
    float wm[6]; float summ = 0.f;
    for (int k = 0; k < nm; k++) {
        float d = fabsf(sfm - (float)(jm0 + k)) / ks;
        float wv = fmaxf(0.f, 1.f - d);
        wm[k] = wv; summ += wv;
    }
    for (int k = 0; k < nm; k++) wm[k] /= summ;

    float ar = 0.f, ai = 0.f;
    for (int kl = 0; kl < 4; kl++) {
        if (wl[kl] == 0.f) continue;
        int jl = jl0 + kl;
        for (int km = 0; km < nm; km++) {
            float wgt = wl[kl] * wm[km];
            int jm = jm0 + km;
            float r, i2;
            if (jm >= 255) {
                int mm = jm - 255;
                r  = g_fr[(mm * 256 + jl) * 32 + c];
                i2 = g_fi[(mm * 256 + jl) * 32 + c];
            } else {
                int mm = 255 - jm;
                float s = (mm & 1) ? -1.f : 1.f;
                r  =  s * g_fr[(mm * 256 + jl) * 32 + c];
                i2 = -s * g_fi[(mm * 256 + jl) * 32 + c];
            }
            ar += wgt * r; ai += wgt * i2;
        }
    }
    g_Ar[(lo * 255 + mo) * 32 + c] = ar;
    g_Ai[(lo * 255 + mo) * 32 + c] = ai;
}

// ---------------- per-l complex channel mix ----------------
__global__ void k_conv() {
    int l = blockIdx.x;
    int tid = threadIdx.x;           // 256
    int o = tid & 31, mg = tid >> 5;
    __shared__ float Wrs[1024], Wis[1024], Ars[256], Ais[256];
    for (int k = 0; k < 4; k++) {
        Wrs[tid + k * 256] = g_Wr[l * 1024 + tid + k * 256];
        Wis[tid + k * 256] = g_Wi[l * 1024 + tid + k * 256];
    }
    __syncthreads();
    for (int mb = 0; mb < 255; mb += 8) {
        int r = tid >> 5, cc = tid & 31;
        int mm = mb + r;
        if (mm < 255) {
            Ars[tid] = g_Ar[(l * 255 + mm) * 32 + cc];
            Ais[tid] = g_Ai[(l * 255 + mm) * 32 + cc];
        }
        __syncthreads();
        int mi = mb + mg;
        if (mi < 255) {
            float accr = 0.f, acci = 0.f;
            #pragma unroll
            for (int i = 0; i < 32; i++) {
                float ar = Ars[mg * 32 + i], ai = Ais[mg * 32 + i];
                float wr = Wrs[i * 32 + o],  wi = Wis[i * 32 + o];
                accr += ar * wr - ai * wi;
                acci += ar * wi + ai * wr;
            }
            g_Br[(mi * 128 + l) * 32 + o] = accr;
            g_Bi[(mi * 128 + l) * 32 + o] = acci;
        }
        __syncthreads();
    }
}

// ---------------- inverse Legendre: G[mi][t][c] = sum_{l<128} B[mi][l][c]*sgn*P[|m|][l][t] ----------------
__global__ void k_leginv() {
    int tq = blockIdx.x, mi = blockIdx.y;
    int c = threadIdx.x, tg = threadIdx.y;
    int tid = tg * 32 + c;
    int m = mi - 127;
    int mabs = m < 0 ? -m : m;
    float s = (m < 0 && (mabs & 1)) ? -1.f : 1.f;
    int t0 = tq * 64;
    __shared__ float Ps[32 * 64], Brs[32 * 32], Bis[32 * 32];
    float accr[8], acci[8];
    #pragma unroll
    for (int k = 0; k < 8; k++) { accr[k] = 0.f; acci[k] = 0.f; }
    int lc0 = mabs >> 5;   // chunks fully below |m| are exact zeros
    for (int lc = lc0; lc < 4; lc++) {
        int lb = lc * 32;
        for (int k = 0; k < 8; k++) {
            int i = tid + k * 256;
            int ll = i >> 6, tt = i & 63;
            Ps[i] = g_P[(mabs * 256 + lb + ll) * 256 + t0 + tt];
        }
        for (int k = 0; k < 4; k++) {
            int i = tid + k * 256;
            int ll = i >> 5, cc = i & 31;
            Brs[i] = s * g_Br[(mi * 128 + lb + ll) * 32 + cc];
            Bis[i] = s * g_Bi[(mi * 128 + lb + ll) * 32 + cc];
        }
        __syncthreads();
        for (int ll = 0; ll < 32; ll++) {
            float br = Brs[ll * 32 + c], bi = Bis[ll * 32 + c];
            #pragma unroll
            for (int k = 0; k < 8; k++) {
                float p = Ps[ll * 64 + tg * 8 + k];
                accr[k] += br * p;
                acci[k] += bi * p;
            }
        }
        __syncthreads();
    }
    for (int k = 0; k < 8; k++) {
        int t = t0 + tg * 8 + k;
        g_Gr[((size_t)mi * 256 + t) * 32 + c] = accr[k];
        g_Gi[((size_t)mi * 256 + t) * 32 + c] = acci[k];
    }
}

// ---------------- fold G over +/-m (tf32-rounded for tensor GEMM) ----------------
__global__ void k_fold2() {
    int mu = blockIdx.y;              // 0..127
    int tid = threadIdx.x;
    int t = blockIdx.x * 8 + (tid >> 5);
    int c = tid & 31;
    size_t tc = (size_t)t * 32 + c;
    float hc, hs;
    float grp = g_Gr[(size_t)(127 + mu) * 8192 + tc];
    float gip = g_Gi[(size_t)(127 + mu) * 8192 + tc];
    if (mu == 0) { hc = grp; hs = 0.f; }
    else {
        float grm = g_Gr[(size_t)(127 - mu) * 8192 + tc];
        float gim = g_Gi[(size_t)(127 - mu) * 8192 + tc];
        hc = grp + grm;
        hs = gim - gip;
    }
    g_Hc[(size_t)mu * 8192 + tc] = tf32r(hc);
    g_Hs[(size_t)mu * 8192 + tc] = tf32r(hs);
}

// ---------------- launch ----------------
extern "C" void kernel_launch(void* const* d_in, const int* in_sizes, int n_in,
                              void* d_out, int out_size) {
    const float* x     = (const float*)d_in[0];
    const float* t_emb = (const float*)d_in[1];
    const float* wr    = (const float*)d_in[2];
    const float* wi    = (const float*)d_in[3];
    const float* w_tr  = (const float*)d_in[4];
    const float* b_tr  = (const float*)d_in[5];
    const float* w_ti  = (const float*)d_in[6];
    const float* b_ti  = (const float*)d_in[7];
    float* out = (float*)d_out;

    k_coef<<<256, 256>>>();
    k_ttab<<<256, 256>>>();
    k_fold1<<<dim3(32, 256), 256>>>(x);
    k_gemm<256, 0><<<dim3(4, 128), 256>>>(nullptr);   // 4th launch -> ncu slot
    k_basis<<<256, 256>>>();
    k_tcwmod<<<128, 256>>>(t_emb, w_tr, b_tr, w_ti, b_ti, wr, wi);
    k_legfwd<<<dim3(4, 256), dim3(32, 8)>>>();
    k_resize<<<dim3(255, 128), 32>>>();
    k_conv<<<128, 256>>>();
    k_leginv<<<dim3(4, 255), dim3(32, 8)>>>();
    k_fold2<<<dim3(32, 128), 256>>>();
    k_gemm<128, 1><<<dim3(4, 128), 256>>>(out);
}

// round 10
// speedup vs baseline: 1.8036x; 1.3632x over previous
#include <cuda_runtime.h>
#include <math.h>

#define PI_D 3.14159265358979323846264338327950288

// Problem sizes: L=256, 2L-1=511, C=32, L_FREQ=128, MF=255, T_DIM=256

__device__ __forceinline__ float tf32r(float x) {
    float y; asm("cvt.rna.tf32.f32 %0, %1;" : "=f"(y) : "f"(x)); return y;
}

#define MMA_TF32(C, A, b0, b1)                                                  \
    asm volatile("mma.sync.aligned.m16n8k8.row.col.f32.tf32.tf32.f32 "          \
                 "{%0,%1,%2,%3}, {%4,%5,%6,%7}, {%8,%9}, {%0,%1,%2,%3};"        \
                 : "+f"(C[0]), "+f"(C[1]), "+f"(C[2]), "+f"(C[3])               \
                 : "r"(A[0]), "r"(A[1]), "r"(A[2]), "r"(A[3]), "r"(b0), "r"(b1))

// ---------------- scratch (device globals; allocation-free) ----------------
__device__ float  g_P [16777216];              // [m][l][t] tf32-rounded, zero for l<m
__device__ float  g_w [256];                   // quadrature weights sin(th)*dang^2
__device__ float  g_cs[256];                   // sqrt((2k+1)/(2k))
__device__ float2 g_ab[65536];                 // [m][l] recurrence coeffs (a,b)
__device__ __align__(16) float2 g_T[65536];    // [k][j] tf32-rounded (cos,sin)(2*pi*k*j/511)
__device__ __align__(16) float  g_xs[2097152]; // [p][t][c] folded+weighted x (sum), tf32
__device__ __align__(16) float  g_xd[2097152]; // [p][t][c] folded+weighted x (diff), tf32
__device__ __align__(16) float  g_Fr[2097152]; // [m][t][c] tf32-rounded
__device__ __align__(16) float  g_Fi[2097152];
__device__ __align__(16) float  g_fr[2097152]; // [m][l][c] flm for m>=0
__device__ __align__(16) float  g_fi[2097152];
__device__ float  g_Ar[1044480];               // [lo][mo][c] resized flm
__device__ float  g_Ai[1044480];
__device__ float  g_Wr[131072];                // [l][i][o] modulated weight
__device__ float  g_Wi[131072];
__device__ __align__(16) float  g_Br[1044480]; // [mi][l][c] after channel mix, tf32
__device__ __align__(16) float  g_Bi[1044480];
__device__ __align__(16) float  g_Gr[2088960]; // [mi][t][c]
__device__ __align__(16) float  g_Gi[2088960];
__device__ __align__(16) float  g_Hc[1048576]; // [mu][t][c] m-folded cos coeff, tf32
__device__ __align__(16) float  g_Hs[1048576]; // [mu][t][c] m-folded sin coeff, tf32

// ---------------- recurrence coefficients + quadrature weights ----------------
__global__ void k_coef() {
    int m = blockIdx.x, l = threadIdx.x;
    if (m == 0) {
        g_cs[l] = (l >= 1) ? sqrtf((2.f * l + 1.f) / (2.f * l)) : 0.f;
        double th = PI_D * (2.0 * l + 1.0) / 511.0;
        double dang = 2.0 * PI_D / 511.0;
        g_w[l] = (float)(sin(th) * dang * dang);
    }
    float2 ab = make_float2(0.f, 0.f);
    if (l >= m + 2) {
        float fl = (float)l, fm = (float)m;
        float denom = fl * fl - fm * fm;
        ab.x = sqrtf((4.f * fl * fl - 1.f) / denom);
        ab.y = sqrtf((2.f * fl + 1.f) * (fl - 1.f - fm) * (fl - 1.f + fm) /
                     ((2.f * fl - 3.f) * denom));
    }
    g_ab[m * 256 + l] = ab;
}

// ---------------- twiddle table (tf32-rounded) ----------------
__global__ void k_ttab() {
    int k = blockIdx.x, j = threadIdx.x;
    int kj = (k * j) % 511;
    double s, c;
    sincos(2.0 * PI_D * (double)kj / 511.0, &s, &c);
    g_T[k * 256 + j] = make_float2(tf32r((float)c), tf32r((float)s));
}

// ---------------- fold x over p-pairs, apply quadrature weight (tf32) ----------------
__global__ void k_fold1(const float* __restrict__ x) {
    int p = blockIdx.y;
    int tid = threadIdx.x;
    int t = blockIdx.x * 8 + (tid >> 5);
    int c = tid & 31;
    float w = g_w[t];
    float a = x[((size_t)t * 511 + p) * 32 + c];
    float xs, xd;
    if (p == 0) { xs = w * a; xd = 0.f; }
    else {
        float b = x[((size_t)t * 511 + (511 - p)) * 32 + c];
        xs = w * (a + b);
        xd = w * (b - a);
    }
    size_t o = ((size_t)p * 256 + t) * 32 + c;
    g_xs[o] = tf32r(xs);
    g_xd[o] = tf32r(xd);
}

// ---------------- tf32 tensor-core dual-GEMM (pipelined, bank-tuned) ----------------
// Cr[m][n] = sum_k cosT[k][m]*B1[k][n];  Ci[m][n] = sum_k sinT[k][m]*B2[k][n]
// MODE 0: B1=g_xs, B2=g_xd -> g_Fr=Cr, g_Fi=Ci (tf32-rounded, feeds legfwd MMA)
// MODE 1: B1=g_Hc, B2=g_Hs -> out[t][p][c]=Cr+Ci, out[t][511-p][c]=Cr-Ci
template<int KTOT, int MODE>
__global__ void __launch_bounds__(256)
k_gemm(float* __restrict__ outp) {
    const float* __restrict__ B1 = (MODE == 0) ? g_xs : g_Hc;
    const float* __restrict__ B2 = (MODE == 0) ? g_xd : g_Hs;
    __shared__ float2 Asm[32][68];     // stride 136 floats == 8 mod 32
    __shared__ float  Bsm1[32][72];    // stride 72 == 8 mod 32
    __shared__ float  Bsm2[32][72];
    const int tid = threadIdx.x;
    const int w = tid >> 5, lane = tid & 31;
    const int g = lane >> 2, t4 = lane & 3;
    const int m0 = blockIdx.x * 64, n0 = blockIdx.y * 64;
    const int warpM = (w >> 1) * 16, warpN = (w & 1) * 32;
    float cr[4][4] = {}, ci[4][4] = {};

    float2 aR[8];
    float4 b1R[2], b2R[2];
    // prologue: load chunk 0 into regs
    #pragma unroll
    for (int p = 0; p < 8; p++) {
        int idx = p * 256 + tid;
        aR[p] = g_T[(idx >> 6) * 256 + m0 + (idx & 63)];
    }
    #pragma unroll
    for (int p = 0; p < 2; p++) {
        int kk = p * 16 + (tid >> 4), nn = (tid & 15) * 4;
        b1R[p] = *(const float4*)&B1[(size_t)kk * 8192 + n0 + nn];
        b2R[p] = *(const float4*)&B2[(size_t)kk * 8192 + n0 + nn];
    }

    for (int k0 = 0; k0 < KTOT; k0 += 32) {
        __syncthreads();
        #pragma unroll
        for (int p = 0; p < 8; p++) {
            int idx = p * 256 + tid;
            Asm[idx >> 6][idx & 63] = aR[p];
        }
        #pragma unroll
        for (int p = 0; p < 2; p++) {
            int kk = p * 16 + (tid >> 4), nn = (tid & 15) * 4;
            *(float4*)&Bsm1[kk][nn] = b1R[p];
            *(float4*)&Bsm2[kk][nn] = b2R[p];
        }
        __syncthreads();
        if (k0 + 32 < KTOT) {   // prefetch next chunk; latency hidden behind MMAs
            int k1 = k0 + 32;
            #pragma unroll
            for (int p = 0; p < 8; p++) {
                int idx = p * 256 + tid;
                aR[p] = g_T[(k1 + (idx >> 6)) * 256 + m0 + (idx & 63)];
            }
            #pragma unroll
            for (int p = 0; p < 2; p++) {
                int kk = p * 16 + (tid >> 4), nn = (tid & 15) * 4;
                b1R[p] = *(const float4*)&B1[(size_t)(k1 + kk) * 8192 + n0 + nn];
                b2R[p] = *(const float4*)&B2[(size_t)(k1 + kk) * 8192 + n0 + nn];
            }
        }
        #pragma unroll
        for (int ks = 0; ks < 4; ks++) {
            int kb = ks * 8;
            float2 v00 = Asm[kb + t4][warpM + g];
            float2 v10 = Asm[kb + t4][warpM + g + 8];
            float2 v01 = Asm[kb + t4 + 4][warpM + g];
            float2 v11 = Asm[kb + t4 + 4][warpM + g + 8];
            unsigned ac[4] = {__float_as_uint(v00.x), __float_as_uint(v10.x),
                              __float_as_uint(v01.x), __float_as_uint(v11.x)};
            unsigned as[4] = {__float_as_uint(v00.y), __float_as_uint(v10.y),
                              __float_as_uint(v01.y), __float_as_uint(v11.y)};
            #pragma unroll
            for (int nb = 0; nb < 4; nb++) {
                int nc = warpN + nb * 8 + g;
                unsigned b1a = __float_as_uint(Bsm1[kb + t4][nc]);
                unsigned b1b = __float_as_uint(Bsm1[kb + t4 + 4][nc]);
                unsigned b2a = __float_as_uint(Bsm2[kb + t4][nc]);
                unsigned b2b = __float_as_uint(Bsm2[kb + t4 + 4][nc]);
                MMA_TF32(cr[nb], ac, b1a, b1b);
                MMA_TF32(ci[nb], as, b2a, b2b);
            }
        }
    }

    if (MODE == 0) {
        int m_row = m0 + warpM + g;
        #pragma unroll
        for (int nb = 0; nb < 4; nb++) {
            int n = n0 + warpN + nb * 8 + 2 * t4;
            size_t o0 = (size_t)m_row * 8192 + n;
            size_t o1 = (size_t)(m_row + 8) * 8192 + n;
            *(float2*)&g_Fr[o0] = make_float2(tf32r(cr[nb][0]), tf32r(cr[nb][1]));
            *(float2*)&g_Fr[o1] = make_float2(tf32r(cr[nb][2]), tf32r(cr[nb][3]));
            *(float2*)&g_Fi[o0] = make_float2(tf32r(ci[nb][0]), tf32r(ci[nb][1]));
            *(float2*)&g_Fi[o1] = make_float2(tf32r(ci[nb][2]), tf32r(ci[nb][3]));
        }
    } else {
        int p0r = m0 + warpM + g;
        int p1r = p0r + 8;
        #pragma unroll
        for (int nb = 0; nb < 4; nb++) {
            int n = n0 + warpN + nb * 8 + 2 * t4;
            int t = n >> 5, c = n & 31;
            float2 vp0 = make_float2(cr[nb][0] + ci[nb][0], cr[nb][1] + ci[nb][1]);
            *(float2*)&outp[((size_t)t * 511 + p0r) * 32 + c] = vp0;
            if (p0r > 0) {
                float2 vm0 = make_float2(cr[nb][0] - ci[nb][0], cr[nb][1] - ci[nb][1]);
                *(float2*)&outp[((size_t)t * 511 + (511 - p0r)) * 32 + c] = vm0;
            }
            float2 vp1 = make_float2(cr[nb][2] + ci[nb][2], cr[nb][3] + ci[nb][3]);
            *(float2*)&outp[((size_t)t * 511 + p1r) * 32 + c] = vp1;
            float2 vm1 = make_float2(cr[nb][2] - ci[nb][2], cr[nb][3] - ci[nb][3]);
            *(float2*)&outp[((size_t)t * 511 + (511 - p1r)) * 32 + c] = vm1;
        }
    }
}

// ---------------- basis: pure-FMA recurrence; stores tf32-rounded P ----------------
__global__ void k_basis() {
    int m = blockIdx.x;
    int t = threadIdx.x;
    __shared__ float  cs[256];
    __shared__ float2 ab[256];
    cs[t] = g_cs[t];
    ab[t] = g_ab[m * 256 + t];
    double th = PI_D * (2.0 * t + 1.0) / 511.0;
    float ct = (float)cos(th), st = (float)sin(th);
    __syncthreads();
    float* Pm = g_P + m * 65536;
    for (int l = 0; l < m; l++) Pm[l * 256 + t] = 0.f;
    float pmm = 0.28209479177387814f;  // sqrt(1/(4*pi))
    for (int k = 1; k <= m; k++) pmm *= -cs[k] * st;
    Pm[m * 256 + t] = tf32r(pmm);
    if (m + 1 < 256) {
        float pl1 = sqrtf(2.f * m + 3.f) * ct * pmm;
        Pm[(m + 1) * 256 + t] = tf32r(pl1);
        float pl2 = pmm;
        for (int l = m + 2; l < 256; l++) {
            float2 c2 = ab[l];
            float p = c2.x * ct * pl1 - c2.y * pl2;
            Pm[l * 256 + t] = tf32r(p);
            pl2 = pl1; pl1 = p;
        }
    }
}

// ---------------- forward Legendre via tf32 MMA ----------------
// flm[m][l][c] = sum_t P[m][l][t]*F[m][t][c].  One block per m.
// M=256 (l) over 8 warps (32 each), N=32 (c), K=256 (t). Dual (Fr,Fi).
// Warps whose entire l-range is < m skip MMA issue (P rows are zero).
__global__ void __launch_bounds__(256)
k_legfwd() {
    const int m = blockIdx.x;
    const int tid = threadIdx.x;
    const int w = tid >> 5, lane = tid & 31;
    const int g = lane >> 2, t4 = lane & 3;
    const int warpM = w * 32;
    __shared__ float As[256][36];    // [l][t], stride 36 == 4 mod 32 (frag bank 4g+t4)
    __shared__ float B1s[32][40];    // [t][c], stride 40 == 8 mod 32
    __shared__ float B2s[32][40];
    float cr[2][4][4] = {}, ci[2][4][4] = {};
    const bool active = (warpM + 31 >= m);
    for (int k0 = 0; k0 < 256; k0 += 32) {
        __syncthreads();
        #pragma unroll
        for (int r = 0; r < 8; r++) {
            int idx = r * 256 + tid;                   // 2048 float4s
            int ll = idx >> 3, tf = (idx & 7) * 4;
            *(float4*)&As[ll][tf] =
                *(const float4*)&g_P[((size_t)m * 256 + ll) * 256 + k0 + tf];
        }
        {
            int kk = tid >> 3, nn = (tid & 7) * 4;
            *(float4*)&B1s[kk][nn] =
                *(const float4*)&g_Fr[((size_t)m * 256 + k0 + kk) * 32 + nn];
            *(float4*)&B2s[kk][nn] =
                *(const float4*)&g_Fi[((size_t)m * 256 + k0 + kk) * 32 + nn];
        }
        __syncthreads();
        if (active) {
            #pragma unroll
            for (int ks = 0; ks < 4; ks++) {
                int kb = ks * 8;
                unsigned a[2][4];
                #pragma unroll
                for (int mf = 0; mf < 2; mf++) {
                    int r0 = warpM + mf * 16 + g;
                    a[mf][0] = __float_as_uint(As[r0][kb + t4]);
                    a[mf][1] = __float_as_uint(As[r0 + 8][kb + t4]);
                    a[mf][2] = __float_as_uint(As[r0][kb + t4 + 4]);
                    a[mf][3] = __float_as_uint(As[r0 + 8][kb + t4 + 4]);
                }
                #pragma unroll
                for (int nb = 0; nb < 4; nb++) {
                    int nc = nb * 8 + g;
                    unsigned b1a = __float_as_uint(B1s[kb + t4][nc]);
                    unsigned b1b = __float_as_uint(B1s[kb + t4 + 4][nc]);
                    unsigned b2a = __float_as_uint(B2s[kb + t4][nc]);
                    unsigned b2b = __float_as_uint(B2s[kb + t4 + 4][nc]);
                    MMA_TF32(cr[0][nb], a[0], b1a, b1b);
                    MMA_TF32(ci[0][nb], a[0], b2a, b2b);
                    MMA_TF32(cr[1][nb], a[1], b1a, b1b);
                    MMA_TF32(ci[1][nb], a[1], b2a, b2b);
                }
            }
        }
    }
    #pragma unroll
    for (int mf = 0; mf < 2; mf++) {
        int l_row = warpM + mf * 16 + g;
        #pragma unroll
        for (int nb = 0; nb < 4; nb++) {
            int c = nb * 8 + 2 * t4;
            size_t o0 = ((size_t)m * 256 + l_row) * 32 + c;
            size_t o1 = ((size_t)m * 256 + l_row + 8) * 32 + c;
            *(float2*)&g_fr[o0] = make_float2(cr[mf][nb][0], cr[mf][nb][1]);
            *(float2*)&g_fr[o1] = make_float2(cr[mf][nb][2], cr[mf][nb][3]);
            *(float2*)&g_fi[o0] = make_float2(ci[mf][nb][0], ci[mf][nb][1]);
            *(float2*)&g_fi[o1] = make_float2(ci[mf][nb][2], ci[mf][nb][3]);
        }
    }
}

// ---------------- time embedding + weight modulation (merged) ----------------
__global__ void k_tcwmod(const float* __restrict__ t_emb,
                         const float* __restrict__ w_tr, const float* __restrict__ b_tr,
                         const float* __restrict__ w_ti, const float* __restrict__ b_ti,
                         const float* __restrict__ wr_in, const float* __restrict__ wi_in) {
    int l = blockIdx.x;           // 0..127
    int tid = threadIdx.x;        // 256
    int lane = tid & 31, wid = tid >> 5;
    __shared__ float sr[8], si[8];
    __shared__ float2 s_tc;
    float e = t_emb[tid];
    float pr = e * w_tr[tid * 128 + l];
    float pi = e * w_ti[tid * 128 + l];
    #pragma unroll
    for (int off = 16; off; off >>= 1) {
        pr += __shfl_down_sync(0xffffffffu, pr, off);
        pi += __shfl_down_sync(0xffffffffu, pi, off);
    }
    if (lane == 0) { sr[wid] = pr; si[wid] = pi; }
    __syncthreads();
    if (tid == 0) {
        float tr = b_tr[l], ti = b_ti[l];
        for (int w = 0; w < 8; w++) { tr += sr[w]; ti += si[w]; }
        s_tc = make_float2(tr, ti);
    }
    __syncthreads();
    float2 tc = s_tc;
    #pragma unroll
    for (int k = 0; k < 4; k++) {
        int io = tid + k * 256;
        float wr = wr_in[l * 1024 + io], wi = wi_in[l * 1024 + io];
        g_Wr[l * 1024 + io] = tc.x * wr - tc.y * wi;
        g_Wi[l * 1024 + io] = tc.x * wi + tc.y * wr;
    }
}

// ---------------- bilinear (antialiased) resize (256,511)->(128,255) ----------------
__global__ void k_resize() {
    int mo = blockIdx.x;   // 0..254
    int lo = blockIdx.y;   // 0..127
    int c  = threadIdx.x;  // 0..31

    float sfl = 2.f * lo + 0.5f;
    int jl0 = 2 * lo - 1;
    float wl[4]; float suml = 0.f;
    #pragma unroll
    for (int k = 0; k < 4; k++) {
        int j = jl0 + k;
        float wv = 0.f;
        if (j >= 0 && j < 256) {
            float d = fabsf(sfl - (float)j) * 0.5f;
            wv = fmaxf(0.f, 1.f - d);
        }
        wl[k] = wv; suml += wv;
    }
    #pragma unroll
    for (int k = 0; k < 4; k++) wl[k] /= suml;

    const float ks = 511.f / 255.f;
    float sfm = ((float)mo + 0.5f) * ks - 0.5f;
    int jm0 = (int)ceilf(sfm - ks);  if (jm0 < 0)   jm0 = 0;
    int jm1 = (int)floorf(sfm + ks); if (jm1 > 510) jm1 = 510;
    int nm = jm1 - jm0 + 1;
    float wm[6]; float summ = 0.f;
    for (int k = 0; k < nm; k++) {
        float d = fabsf(sfm - (float)(jm0 + k)) / ks;
        float wv = fmaxf(0.f, 1.f - d);
        wm[k] = wv; summ += wv;
    }
    for (int k = 0; k < nm; k++) wm[k] /= summ;

    float ar = 0.f, ai = 0.f;
    for (int kl = 0; kl < 4; kl++) {
        if (wl[kl] == 0.f) continue;
        int jl = jl0 + kl;
        for (int km = 0; km < nm; km++) {
            float wgt = wl[kl] * wm[km];
            int jm = jm0 + km;
            float r, i2;
            if (jm >= 255) {
                int mm = jm - 255;
                r  = g_fr[(mm * 256 + jl) * 32 + c];
                i2 = g_fi[(mm * 256 + jl) * 32 + c];
            } else {
                int mm = 255 - jm;
                float s = (mm & 1) ? -1.f : 1.f;
                r  =  s * g_fr[(mm * 256 + jl) * 32 + c];
                i2 = -s * g_fi[(mm * 256 + jl) * 32 + c];
            }
            ar += wgt * r; ai += wgt * i2;
        }
    }
    g_Ar[(lo * 255 + mo) * 32 + c] = ar;
    g_Ai[(lo * 255 + mo) * 32 + c] = ai;
}

// ---------------- per-l complex channel mix (tf32-rounded output) ----------------
__global__ void k_conv() {
    int l = blockIdx.x;
    int tid = threadIdx.x;           // 256
    int o = tid & 31, mg = tid >> 5;
    __shared__ float Wrs[1024], Wis[1024], Ars[256], Ais[256];
    for (int k = 0; k < 4; k++) {
        Wrs[tid + k * 256] = g_Wr[l * 1024 + tid + k * 256];
        Wis[tid + k * 256] = g_Wi[l * 1024 + tid + k * 256];
    }
    __syncthreads();
    for (int mb = 0; mb < 255; mb += 8) {
        int r = tid >> 5, cc = tid & 31;
        int mm = mb + r;
        if (mm < 255) {
            Ars[tid] = g_Ar[(l * 255 + mm) * 32 + cc];
            Ais[tid] = g_Ai[(l * 255 + mm) * 32 + cc];
        }
        __syncthreads();
        int mi = mb + mg;
        if (mi < 255) {
            float accr = 0.f, acci = 0.f;
            #pragma unroll
            for (int i = 0; i < 32; i++) {
                float ar = Ars[mg * 32 + i], ai = Ais[mg * 32 + i];
                float wr = Wrs[i * 32 + o],  wi = Wis[i * 32 + o];
                accr += ar * wr - ai * wi;
                acci += ar * wi + ai * wr;
            }
            g_Br[(mi * 128 + l) * 32 + o] = tf32r(accr);
            g_Bi[(mi * 128 + l) * 32 + o] = tf32r(acci);
        }
        __syncthreads();
    }
}

// ---------------- inverse Legendre via tf32 MMA ----------------
// G[mi][t][c] = sum_l (s*B[mi][l][c]) * P[|m|][l][t].
// Grid (2,255): (tq, mi). M=128 (t) over 8 warps, N=32 (c), K=128 (l), dual.
// K-chunks entirely below |m| skipped (block-uniform; P rows zero).
__global__ void __launch_bounds__(256)
k_leginv() {
    const int tq = blockIdx.x, mi = blockIdx.y;
    const int t0 = tq * 128;
    const int tid = threadIdx.x;
    const int w = tid >> 5, lane = tid & 31;
    const int g = lane >> 2, t4 = lane & 3;
    const int warpM = w * 16;
    const int m = mi - 127;
    const int mabs = m < 0 ? -m : m;
    const float s = (m < 0 && (mabs & 1)) ? -1.f : 1.f;
    __shared__ float As[32][136];   // [l][t], stride 136 == 8 mod 32
    __shared__ float B1s[32][40];   // [l][c]
    __shared__ float B2s[32][40];
    float cr[4][4] = {}, ci[4][4] = {};
    const int k00 = (mabs >> 5) * 32;
    for (int k0 = k00; k0 < 128; k0 += 32) {
        __syncthreads();
        #pragma unroll
        for (int r = 0; r < 4; r++) {
            int idx = r * 256 + tid;                  // 1024 float4s = 32l x 128t
            int ll = idx >> 5, tf = (idx & 31) * 4;
            *(float4*)&As[ll][tf] =
                *(const float4*)&g_P[((size_t)mabs * 256 + k0 + ll) * 256 + t0 + tf];
        }
        {
            int kk = tid >> 3, nn = (tid & 7) * 4;
            float4 v1 = *(const float4*)&g_Br[((size_t)mi * 128 + k0 + kk) * 32 + nn];
            float4 v2 = *(const float4*)&g_Bi[((size_t)mi * 128 + k0 + kk) * 32 + nn];
            v1.x *= s; v1.y *= s; v1.z *= s; v1.w *= s;
            v2.x *= s; v2.y *= s; v2.z *= s; v2.w *= s;
            *(float4*)&B1s[kk][nn] = v1;
            *(float4*)&B2s[kk][nn] = v2;
        }
        __syncthreads();
        #pragma unroll
        for (int ks = 0; ks < 4; ks++) {
            int kb = ks * 8;
            unsigned a[4] = {
                __float_as_uint(As[kb + t4][warpM + g]),
                __float_as_uint(As[kb + t4][warpM + g + 8]),
                __float_as_uint(As[kb + t4 + 4][warpM + g]),
                __float_as_uint(As[kb + t4 + 4][warpM + g + 8])};
            #pragma unroll
            for (int nb = 0; nb < 4; nb++) {
                int nc = nb * 8 + g;
                unsigned b1a = __float_as_uint(B1s[kb + t4][nc]);
                unsigned b1b = __float_as_uint(B1s[kb + t4 + 4][nc]);
                unsigned b2a = __float_as_uint(B2s[kb + t4][nc]);
                unsigned b2b = __float_as_uint(B2s[kb + t4 + 4][nc]);
                MMA_TF32(cr[nb], a, b1a, b1b);
                MMA_TF32(ci[nb], a, b2a, b2b);
            }
        }
    }
    int t_row = t0 + warpM + g;
    #pragma unroll
    for (int nb = 0; nb < 4; nb++) {
        int c = nb * 8 + 2 * t4;
        size_t o0 = ((size_t)mi * 256 + t_row) * 32 + c;
        size_t o1 = ((size_t)mi * 256 + t_row + 8) * 32 + c;
        *(float2*)&g_Gr[o0] = make_float2(cr[nb][0], cr[nb][1]);
        *(float2*)&g_Gr[o1] = make_float2(cr[nb][2], cr[nb][3]);
        *(float2*)&g_Gi[o0] = make_float2(ci[nb][0], ci[nb][1]);
        *(float2*)&g_Gi[o1] = make_float2(ci[nb][2], ci[nb][3]);
    }
}

// ---------------- fold G over +/-m (tf32-rounded for inverse GEMM) ----------------
__global__ void k_fold2() {
    int mu = blockIdx.y;              // 0..127
    int tid = threadIdx.x;
    int t = blockIdx.x * 8 + (tid >> 5);
    int c = tid & 31;
    size_t tc = (size_t)t * 32 + c;
    float hc, hs;
    float grp = g_Gr[(size_t)(127 + mu) * 8192 + tc];
    float gip = g_Gi[(size_t)(127 + mu) * 8192 + tc];
    if (mu == 0) { hc = grp; hs = 0.f; }
    else {
        float grm = g_Gr[(size_t)(127 - mu) * 8192 + tc];
        float gim = g_Gi[(size_t)(127 - mu) * 8192 + tc];
        hc = grp + grm;
        hs = gim - gip;
    }
    g_Hc[(size_t)mu * 8192 + tc] = tf32r(hc);
    g_Hs[(size_t)mu * 8192 + tc] = tf32r(hs);
}

// ---------------- launch ----------------
extern "C" void kernel_launch(void* const* d_in, const int* in_sizes, int n_in,
                              void* d_out, int out_size) {
    const float* x     = (const float*)d_in[0];
    const float* t_emb = (const float*)d_in[1];
    const float* wr    = (const float*)d_in[2];
    const float* wi    = (const float*)d_in[3];
    const float* w_tr  = (const float*)d_in[4];
    const float* b_tr  = (const float*)d_in[5];
    const float* w_ti  = (const float*)d_in[6];
    const float* b_ti  = (const float*)d_in[7];
    float* out = (float*)d_out;

    k_coef<<<256, 256>>>();
    k_ttab<<<256, 256>>>();
    k_fold1<<<dim3(32, 256), 256>>>(x);
    k_gemm<256, 0><<<dim3(4, 128), 256>>>(nullptr);   // 4th launch -> ncu slot
    k_basis<<<256, 256>>>();
    k_tcwmod<<<128, 256>>>(t_emb, w_tr, b_tr, w_ti, b_ti, wr, wi);
    k_legfwd<<<256, 256>>>();
    k_resize<<<dim3(255, 128), 32>>>();
    k_conv<<<128, 256>>>();
    k_leginv<<<dim3(2, 255), 256>>>();
    k_fold2<<<dim3(32, 128), 256>>>();
    k_gemm<128, 1><<<dim3(4, 128), 256>>>(out);
}

// round 16
// speedup vs baseline: 1.8832x; 1.0442x over previous
#include <cuda_runtime.h>
#include <math.h>

#define PI_D 3.14159265358979323846264338327950288

// Problem sizes: L=256, 2L-1=511, C=32, L_FREQ=128, MF=255, T_DIM=256

__device__ __forceinline__ float tf32r(float x) {
    float y; asm("cvt.rna.tf32.f32 %0, %1;" : "=f"(y) : "f"(x)); return y;
}

#define MMA_TF32(C, A, b0, b1)                                                  \
    asm volatile("mma.sync.aligned.m16n8k8.row.col.f32.tf32.tf32.f32 "          \
                 "{%0,%1,%2,%3}, {%4,%5,%6,%7}, {%8,%9}, {%0,%1,%2,%3};"        \
                 : "+f"(C[0]), "+f"(C[1]), "+f"(C[2]), "+f"(C[3])               \
                 : "r"(A[0]), "r"(A[1]), "r"(A[2]), "r"(A[3]), "r"(b0), "r"(b1))

#define CP16(dst_u32, src_ptr)                                                  \
    asm volatile("cp.async.cg.shared.global [%0], [%1], 16;"                    \
                 :: "r"(dst_u32), "l"(src_ptr))
#define CP_COMMIT() asm volatile("cp.async.commit_group;" ::: "memory")
#define CP_WAIT0()  asm volatile("cp.async.wait_group 0;" ::: "memory")

// ---------------- scratch (device globals; allocation-free) ----------------
__device__ float  g_P [16777216];              // [m][l][t] tf32-rounded, zero for l<m
__device__ float  g_w [256];                   // quadrature weights sin(th)*dang^2
__device__ float  g_cs[256];                   // sqrt((2k+1)/(2k))
__device__ float2 g_ab[65536];                 // [m][l] recurrence coeffs (a,b)
__device__ __align__(16) float2 g_T[65536];    // [k][j] tf32-rounded (cos,sin)(2*pi*k*j/511)
__device__ __align__(16) float  g_xs[2097152]; // [p][t][c] folded+weighted x (sum), tf32
__device__ __align__(16) float  g_xd[2097152]; // [p][t][c] folded+weighted x (diff), tf32
__device__ __align__(16) float  g_Fr[2097152]; // [m][t][c] tf32-rounded
__device__ __align__(16) float  g_Fi[2097152];
__device__ __align__(16) float  g_fr[2097152]; // [m][l][c] flm for m>=0
__device__ __align__(16) float  g_fi[2097152];
__device__ float  g_Ar[1044480];               // [lo][mo][c] resized flm
__device__ float  g_Ai[1044480];
__device__ float  g_Wr[131072];                // [l][i][o] modulated weight
__device__ float  g_Wi[131072];
__device__ __align__(16) float  g_Br[1044480]; // [mi][l][c] after channel mix, tf32
__device__ __align__(16) float  g_Bi[1044480];
__device__ __align__(16) float  g_Gr[2088960]; // [mi][t][c]
__device__ __align__(16) float  g_Gi[2088960];
__device__ __align__(16) float  g_Hc[1048576]; // [mu][t][c] m-folded cos coeff, tf32
__device__ __align__(16) float  g_Hs[1048576]; // [mu][t][c] m-folded sin coeff, tf32

// ---------------- coef + twiddle table (merged; independent halves) ----------------
__global__ void k_coefttab() {
    if (blockIdx.x < 256) {
        int m = blockIdx.x, l = threadIdx.x;
        if (m == 0) {
            g_cs[l] = (l >= 1) ? sqrtf((2.f * l + 1.f) / (2.f * l)) : 0.f;
            double th = PI_D * (2.0 * l + 1.0) / 511.0;
            double dang = 2.0 * PI_D / 511.0;
            g_w[l] = (float)(sin(th) * dang * dang);
        }
        float2 ab = make_float2(0.f, 0.f);
        if (l >= m + 2) {
            float fl = (float)l, fm = (float)m;
            float denom = fl * fl - fm * fm;
            ab.x = sqrtf((4.f * fl * fl - 1.f) / denom);
            ab.y = sqrtf((2.f * fl + 1.f) * (fl - 1.f - fm) * (fl - 1.f + fm) /
                         ((2.f * fl - 3.f) * denom));
        }
        g_ab[m * 256 + l] = ab;
    } else {
        int k = blockIdx.x - 256, j = threadIdx.x;
        int kj = (k * j) % 511;
        double s, c;
        sincos(2.0 * PI_D * (double)kj / 511.0, &s, &c);
        g_T[k * 256 + j] = make_float2(tf32r((float)c), tf32r((float)s));
    }
}

// ---------------- fold x over p-pairs, apply quadrature weight (tf32) ----------------
__global__ void k_fold1(const float* __restrict__ x) {
    int p = blockIdx.y;
    int tid = threadIdx.x;
    int t = blockIdx.x * 8 + (tid >> 5);
    int c = tid & 31;
    float w = g_w[t];
    float a = x[((size_t)t * 511 + p) * 32 + c];
    float xs, xd;
    if (p == 0) { xs = w * a; xd = 0.f; }
    else {
        float b = x[((size_t)t * 511 + (511 - p)) * 32 + c];
        xs = w * (a + b);
        xd = w * (b - a);
    }
    size_t o = ((size_t)p * 256 + t) * 32 + c;
    g_xs[o] = tf32r(xs);
    g_xd[o] = tf32r(xd);
}

// ---------------- tf32 tensor-core dual-GEMM, 64x128 tile, cp.async dbl-buffer ----------------
// Cr[m][n] = sum_k cosT[k][m]*B1[k][n];  Ci[m][n] = sum_k sinT[k][m]*B2[k][n]
// MODE 0: B1=g_xs, B2=g_xd -> g_Fr=Cr, g_Fi=Ci (tf32-rounded)
// MODE 1: B1=g_Hc, B2=g_Hs -> out[t][p][c]=Cr+Ci, out[t][511-p][c]=Cr-Ci
// Warp tile 32x32 (mf=2, nb=4): 256 smem bytes/MMA.
// Dynamic smem: A[2][32][68]f2 + B1[2][32][136]f + B2[2][32][136]f = 104448 B.
// A tile = 32 k-rows x 64 float2 = 16384 B = 1024 float4 (32 float4 per row).
#define GEMM_SMEM 104448
template<int KTOT, int MODE>
__global__ void __launch_bounds__(256, 2)
k_gemm(float* __restrict__ outp) {
    const float* __restrict__ B1 = (MODE == 0) ? g_xs : g_Hc;
    const float* __restrict__ B2 = (MODE == 0) ? g_xd : g_Hs;
    extern __shared__ __align__(16) char smemraw[];
    float2* Abuf  = (float2*)smemraw;                  // [2][32][68]
    float*  B1buf = (float*)(smemraw + 34816);         // [2][32][136]
    float*  B2buf = (float*)(smemraw + 69632);         // [2][32][136]
    const int tid = threadIdx.x;
    const int w = tid >> 5, lane = tid & 31;
    const int g = lane >> 2, t4 = lane & 3;
    const int m0 = blockIdx.x * 64, n0 = blockIdx.y * 128;
    const int warpM = (w >> 2) * 32, warpN = (w & 3) * 32;
    float cr[2][4][4] = {}, ci[2][4][4] = {};
    const int NCH = KTOT / 32;

    // staging: chunk c -> buffer b (all via cp.async, one group per chunk)
    auto stage = [&](int c, int b) {
        #pragma unroll
        for (int p = 0; p < 4; p++) {              // A: 1024 float4 (32 rows x 32 f4)
            int idx = p * 256 + tid;
            int kk = idx >> 5, mm4 = idx & 31;     // mm4: which pair of float2s in row
            const float2* src = &g_T[(c * 32 + kk) * 256 + m0 + mm4 * 2];
            unsigned dst = (unsigned)__cvta_generic_to_shared(
                &Abuf[b * 2176 + kk * 68 + mm4 * 2]);
            CP16(dst, src);
        }
        #pragma unroll
        for (int p = 0; p < 4; p++) {              // B1/B2: 1024 float4 each
            int idx = p * 256 + tid;
            int kk = idx >> 5, nn = (idx & 31) * 4;
            size_t go = (size_t)(c * 32 + kk) * 8192 + n0 + nn;
            unsigned d1 = (unsigned)__cvta_generic_to_shared(
                &B1buf[b * 4352 + kk * 136 + nn]);
            unsigned d2 = (unsigned)__cvta_generic_to_shared(
                &B2buf[b * 4352 + kk * 136 + nn]);
            CP16(d1, &B1[go]);
            CP16(d2, &B2[go]);
        }
        CP_COMMIT();
    };

    stage(0, 0);
    for (int c = 0; c < NCH; c++) {
        CP_WAIT0();
        __syncthreads();
        if (c + 1 < NCH) stage(c + 1, (c + 1) & 1);
        const int bb = c & 1;
        const float2* As = &Abuf[bb * 2176];
        const float*  B1s = &B1buf[bb * 4352];
        const float*  B2s = &B2buf[bb * 4352];
        #pragma unroll
        for (int ks = 0; ks < 4; ks++) {
            int kb = ks * 8;
            unsigned ac[2][4], as_[2][4];
            #pragma unroll
            for (int mf = 0; mf < 2; mf++) {
                int r0 = warpM + mf * 16 + g;
                float2 v00 = As[(kb + t4) * 68 + r0];
                float2 v10 = As[(kb + t4) * 68 + r0 + 8];
                float2 v01 = As[(kb + t4 + 4) * 68 + r0];
                float2 v11 = As[(kb + t4 + 4) * 68 + r0 + 8];
                ac[mf][0] = __float_as_uint(v00.x); ac[mf][1] = __float_as_uint(v10.x);
                ac[mf][2] = __float_as_uint(v01.x); ac[mf][3] = __float_as_uint(v11.x);
                as_[mf][0] = __float_as_uint(v00.y); as_[mf][1] = __float_as_uint(v10.y);
                as_[mf][2] = __float_as_uint(v01.y); as_[mf][3] = __float_as_uint(v11.y);
            }
            #pragma unroll
            for (int nb = 0; nb < 4; nb++) {
                int nc = warpN + nb * 8 + g;
                unsigned b1a = __float_as_uint(B1s[(kb + t4) * 136 + nc]);
                unsigned b1b = __float_as_uint(B1s[(kb + t4 + 4) * 136 + nc]);
                unsigned b2a = __float_as_uint(B2s[(kb + t4) * 136 + nc]);
                unsigned b2b = __float_as_uint(B2s[(kb + t4 + 4) * 136 + nc]);
                MMA_TF32(cr[0][nb], ac[0], b1a, b1b);
                MMA_TF32(cr[1][nb], ac[1], b1a, b1b);
                MMA_TF32(ci[0][nb], as_[0], b2a, b2b);
                MMA_TF32(ci[1][nb], as_[1], b2a, b2b);
            }
        }
        __syncthreads();
    }

    if (MODE == 0) {
        #pragma unroll
        for (int mf = 0; mf < 2; mf++) {
            int m_row = m0 + warpM + mf * 16 + g;
            #pragma unroll
            for (int nb = 0; nb < 4; nb++) {
                int n = n0 + warpN + nb * 8 + 2 * t4;
                size_t o0 = (size_t)m_row * 8192 + n;
                size_t o1 = (size_t)(m_row + 8) * 8192 + n;
                *(float2*)&g_Fr[o0] = make_float2(tf32r(cr[mf][nb][0]), tf32r(cr[mf][nb][1]));
                *(float2*)&g_Fr[o1] = make_float2(tf32r(cr[mf][nb][2]), tf32r(cr[mf][nb][3]));
                *(float2*)&g_Fi[o0] = make_float2(tf32r(ci[mf][nb][0]), tf32r(ci[mf][nb][1]));
                *(float2*)&g_Fi[o1] = make_float2(tf32r(ci[mf][nb][2]), tf32r(ci[mf][nb][3]));
            }
        }
    } else {
        #pragma unroll
        for (int mf = 0; mf < 2; mf++) {
            int p0r = m0 + warpM + mf * 16 + g;
            int p1r = p0r + 8;
            #pragma unroll
            for (int nb = 0; nb < 4; nb++) {
                int n = n0 + warpN + nb * 8 + 2 * t4;
                int t = n >> 5, c = n & 31;
                float2 vp0 = make_float2(cr[mf][nb][0] + ci[mf][nb][0],
                                         cr[mf][nb][1] + ci[mf][nb][1]);
                *(float2*)&outp[((size_t)t * 511 + p0r) * 32 + c] = vp0;
                if (p0r > 0) {
                    float2 vm0 = make_float2(cr[mf][nb][0] - ci[mf][nb][0],
                                             cr[mf][nb][1] - ci[mf][nb][1]);
                    *(float2*)&outp[((size_t)t * 511 + (511 - p0r)) * 32 + c] = vm0;
                }
                float2 vp1 = make_float2(cr[mf][nb][2] + ci[mf][nb][2],
                                         cr[mf][nb][3] + ci[mf][nb][3]);
                *(float2*)&outp[((size_t)t * 511 + p1r) * 32 + c] = vp1;
                float2 vm1 = make_float2(cr[mf][nb][2] - ci[mf][nb][2],
                                         cr[mf][nb][3] - ci[mf][nb][3]);
                *(float2*)&outp[((size_t)t * 511 + (511 - p1r)) * 32 + c] = vm1;
            }
        }
    }
}

// ---------------- basis: pure-FMA recurrence; stores tf32-rounded P ----------------
__global__ void k_basis() {
    int m = blockIdx.x;
    int t = threadIdx.x;
    __shared__ float  cs[256];
    __shared__ float2 ab[256];
    cs[t] = g_cs[t];
    ab[t] = g_ab[m * 256 + t];
    double th = PI_D * (2.0 * t + 1.0) / 511.0;
    float ct = (float)cos(th), st = (float)sin(th);
    __syncthreads();
    float* Pm = g_P + m * 65536;
    for (int l = 0; l < m; l++) Pm[l * 256 + t] = 0.f;
    float pmm = 0.28209479177387814f;  // sqrt(1/(4*pi))
    for (int k = 1; k <= m; k++) pmm *= -cs[k] * st;
    Pm[m * 256 + t] = tf32r(pmm);
    if (m + 1 < 256) {
        float pl1 = sqrtf(2.f * m + 3.f) * ct * pmm;
        Pm[(m + 1) * 256 + t] = tf32r(pl1);
        float pl2 = pmm;
        for (int l = m + 2; l < 256; l++) {
            float2 c2 = ab[l];
            float p = c2.x * ct * pl1 - c2.y * pl2;
            Pm[l * 256 + t] = tf32r(p);
            pl2 = pl1; pl1 = p;
        }
    }
}

// ---------------- forward Legendre via tf32 MMA ----------------
__global__ void __launch_bounds__(256)
k_legfwd() {
    const int m = blockIdx.x;
    const int tid = threadIdx.x;
    const int w = tid >> 5, lane = tid & 31;
    const int g = lane >> 2, t4 = lane & 3;
    const int warpM = w * 32;
    __shared__ float As[256][36];    // [l][t]
    __shared__ float B1s[32][40];    // [t][c]
    __shared__ float B2s[32][40];
    float cr[2][4][4] = {}, ci[2][4][4] = {};
    const bool active = (warpM + 31 >= m);
    for (int k0 = 0; k0 < 256; k0 += 32) {
        __syncthreads();
        #pragma unroll
        for (int r = 0; r < 8; r++) {
            int idx = r * 256 + tid;
            int ll = idx >> 3, tf = (idx & 7) * 4;
            *(float4*)&As[ll][tf] =
                *(const float4*)&g_P[((size_t)m * 256 + ll) * 256 + k0 + tf];
        }
        {
            int kk = tid >> 3, nn = (tid & 7) * 4;
            *(float4*)&B1s[kk][nn] =
                *(const float4*)&g_Fr[((size_t)m * 256 + k0 + kk) * 32 + nn];
            *(float4*)&B2s[kk][nn] =
                *(const float4*)&g_Fi[((size_t)m * 256 + k0 + kk) * 32 + nn];
        }
        __syncthreads();
        if (active) {
            #pragma unroll
            for (int ks = 0; ks < 4; ks++) {
                int kb = ks * 8;
                unsigned a[2][4];
                #pragma unroll
                for (int mf = 0; mf < 2; mf++) {
                    int r0 = warpM + mf * 16 + g;
                    a[mf][0] = __float_as_uint(As[r0][kb + t4]);
                    a[mf][1] = __float_as_uint(As[r0 + 8][kb + t4]);
                    a[mf][2] = __float_as_uint(As[r0][kb + t4 + 4]);
                    a[mf][3] = __float_as_uint(As[r0 + 8][kb + t4 + 4]);
                }
                #pragma unroll
                for (int nb = 0; nb < 4; nb++) {
                    int nc = nb * 8 + g;
                    unsigned b1a = __float_as_uint(B1s[kb + t4][nc]);
                    unsigned b1b = __float_as_uint(B1s[kb + t4 + 4][nc]);
                    unsigned b2a = __float_as_uint(B2s[kb + t4][nc]);
                    unsigned b2b = __float_as_uint(B2s[kb + t4 + 4][nc]);
                    MMA_TF32(cr[0][nb], a[0], b1a, b1b);
                    MMA_TF32(ci[0][nb], a[0], b2a, b2b);
                    MMA_TF32(cr[1][nb], a[1], b1a, b1b);
                    MMA_TF32(ci[1][nb], a[1], b2a, b2b);
                }
            }
        }
    }
    #pragma unroll
    for (int mf = 0; mf < 2; mf++) {
        int l_row = warpM + mf * 16 + g;
        #pragma unroll
        for (int nb = 0; nb < 4; nb++) {
            int c = nb * 8 + 2 * t4;
            size_t o0 = ((size_t)m * 256 + l_row) * 32 + c;
            size_t o1 = ((size_t)m * 256 + l_row + 8) * 32 + c;
            *(float2*)&g_fr[o0] = make_float2(cr[mf][nb][0], cr[mf][nb][1]);
            *(float2*)&g_fr[o1] = make_float2(cr[mf][nb][2], cr[mf][nb][3]);
            *(float2*)&g_fi[o0] = make_float2(ci[mf][nb][0], ci[mf][nb][1]);
            *(float2*)&g_fi[o1] = make_float2(ci[mf][nb][2], ci[mf][nb][3]);
        }
    }
}

// ---------------- time embedding + weight modulation (merged) ----------------
__global__ void k_tcwmod(const float* __restrict__ t_emb,
                         const float* __restrict__ w_tr, const float* __restrict__ b_tr,
                         const float* __restrict__ w_ti, const float* __restrict__ b_ti,
                         const float* __restrict__ wr_in, const float* __restrict__ wi_in) {
    int l = blockIdx.x;           // 0..127
    int tid = threadIdx.x;        // 256
    int lane = tid & 31, wid = tid >> 5;
    __shared__ float sr[8], si[8];
    __shared__ float2 s_tc;
    float e = t_emb[tid];
    float pr = e * w_tr[tid * 128 + l];
    float pi = e * w_ti[tid * 128 + l];
    #pragma unroll
    for (int off = 16; off; off >>= 1) {
        pr += __shfl_down_sync(0xffffffffu, pr, off);
        pi += __shfl_down_sync(0xffffffffu, pi, off);
    }
    if (lane == 0) { sr[wid] = pr; si[wid] = pi; }
    __syncthreads();
    if (tid == 0) {
        float tr = b_tr[l], ti = b_ti[l];
        for (int w = 0; w < 8; w++) { tr += sr[w]; ti += si[w]; }
        s_tc = make_float2(tr, ti);
    }
    __syncthreads();
    float2 tc = s_tc;
    #pragma unroll
    for (int k = 0; k < 4; k++) {
        int io = tid + k * 256;
        float wr = wr_in[l * 1024 + io], wi = wi_in[l * 1024 + io];
        g_Wr[l * 1024 + io] = tc.x * wr - tc.y * wi;
        g_Wi[l * 1024 + io] = tc.x * wi + tc.y * wr;
    }
}

// ---------------- bilinear (antialiased) resize (256,511)->(128,255) ----------------
__global__ void k_resize() {
    int mo = blockIdx.x;   // 0..254
    int lo = blockIdx.y;   // 0..127
    int c  = threadIdx.x;  // 0..31

    float sfl = 2.f * lo + 0.5f;
    int jl0 = 2 * lo - 1;
    float wl[4]; float suml = 0.f;
    #pragma unroll
    for (int k = 0; k < 4; k++) {
        int j = jl0 + k;
        float wv = 0.f;
        if (j >= 0 && j < 256) {
            float d = fabsf(sfl - (float)j) * 0.5f;
            wv = fmaxf(0.f, 1.f - d);
        }
        wl[k] = wv; suml += wv;
    }
    #pragma unroll
    for (int k = 0; k < 4; k++) wl[k] /= suml;

    const float ks = 511.f / 255.f;
    float sfm = ((float)mo + 0.5f) * ks - 0.5f;
    int jm0 = (int)ceilf(sfm - ks);  if (jm0 < 0)   jm0 = 0;
    int jm1 = (int)floorf(sfm + ks); if (jm1 > 510) jm1 = 510;
    int nm = jm1 - jm0 + 1;
    float wm[6]; float summ = 0.f;
    for (int k = 0; k < nm; k++) {
        float d = fabsf(sfm - (float)(jm0 + k)) / ks;
        float wv = fmaxf(0.f, 1.f - d);
        wm[k] = wv; summ += wv;
    }
    for (int k = 0; k < nm; k++) wm[k] /= summ;

    float ar = 0.f, ai = 0.f;
    for (int kl = 0; kl < 4; kl++) {
        if (wl[kl] == 0.f) continue;
        int jl = jl0 + kl;
        for (int km = 0; km < nm; km++) {
            float wgt = wl[kl] * wm[km];
            int jm = jm0 + km;
            float r, i2;
            if (jm >= 255) {
                int mm = jm - 255;
                r  = g_fr[(mm * 256 + jl) * 32 + c];
                i2 = g_fi[(mm * 256 + jl) * 32 + c];
            } else {
                int mm = 255 - jm;
                float s = (mm & 1) ? -1.f : 1.f;
                r  =  s * g_fr[(mm * 256 + jl) * 32 + c];
                i2 = -s * g_fi[(mm * 256 + jl) * 32 + c];
            }
            ar += wgt * r; ai += wgt * i2;
        }
    }
    g_Ar[(lo * 255 + mo) * 32 + c] = ar;
    g_Ai[(lo * 255 + mo) * 32 + c] = ai;
}

// ---------------- per-l complex channel mix (tf32-rounded output) ----------------
__global__ void k_conv() {
    int l = blockIdx.x;
    int tid = threadIdx.x;           // 256
    int o = tid & 31, mg = tid >> 5;
    __shared__ float Wrs[1024], Wis[1024], Ars[256], Ais[256];
    for (int k = 0; k < 4; k++) {
        Wrs[tid + k * 256] = g_Wr[l * 1024 + tid + k * 256];
        Wis[tid + k * 256] = g_Wi[l * 1024 + tid + k * 256];
    }
    __syncthreads();
    for (int mb = 0; mb < 255; mb += 8) {
        int r = tid >> 5, cc = tid & 31;
        int mm = mb + r;
        if (mm < 255) {
            Ars[tid] = g_Ar[(l * 255 + mm) * 32 + cc];
            Ais[tid] = g_Ai[(l * 255 + mm) * 32 + cc];
        }
        __syncthreads();
        int mi = mb + mg;
        if (mi < 255) {
            float accr = 0.f, acci = 0.f;
            #pragma unroll
            for (int i = 0; i < 32; i++) {
                float ar = Ars[mg * 32 + i], ai = Ais[mg * 32 + i];
                float wr = Wrs[i * 32 + o],  wi = Wis[i * 32 + o];
                accr += ar * wr - ai * wi;
                acci += ar * wi + ai * wr;
            }
            g_Br[(mi * 128 + l) * 32 + o] = tf32r(accr);
            g_Bi[(mi * 128 + l) * 32 + o] = tf32r(acci);
        }
        __syncthreads();
    }
}

// ---------------- inverse Legendre via tf32 MMA ----------------
__global__ void __launch_bounds__(256)
k_leginv() {
    const int tq = blockIdx.x, mi = blockIdx.y;
    const int t0 = tq * 128;
    const int tid = threadIdx.x;
    const int w = tid >> 5, lane = tid & 31;
    const int g = lane >> 2, t4 = lane & 3;
    const int warpM = w * 16;
    const int m = mi - 127;
    const int mabs = m < 0 ? -m : m;
    const float s = (m < 0 && (mabs & 1)) ? -1.f : 1.f;
    __shared__ float As[32][136];   // [l][t]
    __shared__ float B1s[32][40];   // [l][c]
    __shared__ float B2s[32][40];
    float cr[4][4] = {}, ci[4][4] = {};
    const int k00 = (mabs >> 5) * 32;
    for (int k0 = k00; k0 < 128; k0 += 32) {
        __syncthreads();
        #pragma unroll
        for (int r = 0; r < 4; r++) {
            int idx = r * 256 + tid;
            int ll = idx >> 5, tf = (idx & 31) * 4;
            *(float4*)&As[ll][tf] =
                *(const float4*)&g_P[((size_t)mabs * 256 + k0 + ll) * 256 + t0 + tf];
        }
        {
            int kk = tid >> 3, nn = (tid & 7) * 4;
            float4 v1 = *(const float4*)&g_Br[((size_t)mi * 128 + k0 + kk) * 32 + nn];
            float4 v2 = *(const float4*)&g_Bi[((size_t)mi * 128 + k0 + kk) * 32 + nn];
            v1.x *= s; v1.y *= s; v1.z *= s; v1.w *= s;
            v2.x *= s; v2.y *= s; v2.z *= s; v2.w *= s;
            *(float4*)&B1s[kk][nn] = v1;
            *(float4*)&B2s[kk][nn] = v2;
        }
        __syncthreads();
        #pragma unroll
        for (int ks = 0; ks < 4; ks++) {
            int kb = ks * 8;
            unsigned a[4] = {
                __float_as_uint(As[kb + t4][warpM + g]),
                __float_as_uint(As[kb + t4][warpM + g + 8]),
                __float_as_uint(As[kb + t4 + 4][warpM + g]),
                __float_as_uint(As[kb + t4 + 4][warpM + g + 8])};
            #pragma unroll
            for (int nb = 0; nb < 4; nb++) {
                int nc = nb * 8 + g;
                unsigned b1a = __float_as_uint(B1s[kb + t4][nc]);
                unsigned b1b = __float_as_uint(B1s[kb + t4 + 4][nc]);
                unsigned b2a = __float_as_uint(B2s[kb + t4][nc]);
                unsigned b2b = __float_as_uint(B2s[kb + t4 + 4][nc]);
                MMA_TF32(cr[nb], a, b1a, b1b);
                MMA_TF32(ci[nb], a, b2a, b2b);
            }
        }
    }
    int t_row = t0 + warpM + g;
    #pragma unroll
    for (int nb = 0; nb < 4; nb++) {
        int c = nb * 8 + 2 * t4;
        size_t o0 = ((size_t)mi * 256 + t_row) * 32 + c;
        size_t o1 = ((size_t)mi * 256 + t_row + 8) * 32 + c;
        *(float2*)&g_Gr[o0] = make_float2(cr[nb][0], cr[nb][1]);
        *(float2*)&g_Gr[o1] = make_float2(cr[nb][2], cr[nb][3]);
        *(float2*)&g_Gi[o0] = make_float2(ci[nb][0], ci[nb][1]);
        *(float2*)&g_Gi[o1] = make_float2(ci[nb][2], ci[nb][3]);
    }
}

// ---------------- fold G over +/-m (tf32-rounded for inverse GEMM) ----------------
__global__ void k_fold2() {
    int mu = blockIdx.y;              // 0..127
    int tid = threadIdx.x;
    int t = blockIdx.x * 8 + (tid >> 5);
    int c = tid & 31;
    size_t tc = (size_t)t * 32 + c;
    float hc, hs;
    float grp = g_Gr[(size_t)(127 + mu) * 8192 + tc];
    float gip = g_Gi[(size_t)(127 + mu) * 8192 + tc];
    if (mu == 0) { hc = grp; hs = 0.f; }
    else {
        float grm = g_Gr[(size_t)(127 - mu) * 8192 + tc];
        float gim = g_Gi[(size_t)(127 - mu) * 8192 + tc];
        hc = grp + grm;
        hs = gim - gip;
    }
    g_Hc[(size_t)mu * 8192 + tc] = tf32r(hc);
    g_Hs[(size_t)mu * 8192 + tc] = tf32r(hs);
}

// ---------------- launch ----------------
extern "C" void kernel_launch(void* const* d_in, const int* in_sizes, int n_in,
                              void* d_out, int out_size) {
    const float* x     = (const float*)d_in[0];
    const float* t_emb = (const float*)d_in[1];
    const float* wr    = (const float*)d_in[2];
    const float* wi    = (const float*)d_in[3];
    const float* w_tr  = (const float*)d_in[4];
    const float* b_tr  = (const float*)d_in[5];
    const float* w_ti  = (const float*)d_in[6];
    const float* b_ti  = (const float*)d_in[7];
    float* out = (float*)d_out;

    // Unconditional (no static guard — harness rule); host-side, idempotent,
    // graph-capture-safe (not a stream operation).
    cudaFuncSetAttribute(k_gemm<256, 0>, cudaFuncAttributeMaxDynamicSharedMemorySize, GEMM_SMEM);
    cudaFuncSetAttribute(k_gemm<128, 1>, cudaFuncAttributeMaxDynamicSharedMemorySize, GEMM_SMEM);

    k_coefttab<<<512, 256>>>();
    k_fold1<<<dim3(32, 256), 256>>>(x);
    k_basis<<<256, 256>>>();
    k_gemm<256, 0><<<dim3(4, 64), 256, GEMM_SMEM>>>(nullptr);   // 4th launch -> ncu slot
    k_tcwmod<<<128, 256>>>(t_emb, w_tr, b_tr, w_ti, b_ti, wr, wi);
    k_legfwd<<<256, 256>>>();
    k_resize<<<dim3(255, 128), 32>>>();
    k_conv<<<128, 256>>>();
    k_leginv<<<dim3(2, 255), 256>>>();
    k_fold2<<<dim3(32, 128), 256>>>();
    k_gemm<128, 1><<<dim3(4, 64), 256, GEMM_SMEM>>>(out);
}